// round 14
// baseline (speedup 1.0000x reference)
#include <cuda_runtime.h>
#include <cuda_bf16.h>

// ---------------------------------------------------------------------------
// Problem constants
// ---------------------------------------------------------------------------
#define NB    64          // batch
#define ZD    128         // latent dim
#define CIN   8
#define LL    1024        // W*H
#define C0C   256         // attention channels
#define CQKC  32
#define FFC   64          // filters
#define GG    65536       // NB * LL (total positions)

// ---------------------------------------------------------------------------
// Device scratch (allocation-free rule: __device__ globals)
// ---------------------------------------------------------------------------
__device__ __align__(16) float g_x0 [NB * CIN * LL];              //  2 MB
__device__ __align__(16) __nv_bfloat16 g_xah[(size_t)GG * C0C];   // 32 MB
__device__ __align__(16) __nv_bfloat16 g_xal[(size_t)GG * C0C];   // 32 MB
__device__ __align__(16) __nv_bfloat16 g_qkh[(size_t)GG * 64];    //  8 MB [g][q32|k32]
__device__ __align__(16) __nv_bfloat16 g_vTh[(size_t)NB * C0C * LL]; // 32 MB V^T bf16
__device__ __align__(16) __nv_bfloat16 g_atth[(size_t)GG * C0C];  // 32 MB att hi
__device__ __align__(16) __nv_bfloat16 g_attl[(size_t)GG * C0C];  // 32 MB att lo
__device__ __align__(16) float g_x1 [(size_t)GG * FFC];           // 16 MB
// weights
__device__ __align__(16) __nv_bfloat16 g_wqkh[64 * C0C];
__device__ __align__(16) __nv_bfloat16 g_wvh [C0C * C0C];
__device__ __align__(16) __nv_bfloat16 g_w1h [FFC * C0C], g_w1l [FFC * C0C];
__device__ __align__(16) float g_bqk[64];
__device__ float g_pS[C0C * 64];           // reused: x0 moment partials [64][44]
__device__ float g_pQ[C0C * 64];
__device__ __align__(16) float g_scale0[C0C], g_shift0[C0C];
__device__ __align__(16) float g_scale1[FFC], g_shift1[FFC];

// ---------------------------------------------------------------------------
// PTX helpers (sm_80-level only — harness ptxas targets plain sm_100)
// ---------------------------------------------------------------------------
__device__ __forceinline__ unsigned smem_u32(const void* p) {
    unsigned a;
    asm("{ .reg .u64 t; cvta.to.shared.u64 t, %1; cvt.u32.u64 %0, t; }" : "=r"(a) : "l"(p));
    return a;
}
__device__ __forceinline__ void cpasync16(unsigned d, const void* s) {
    asm volatile("cp.async.cg.shared.global [%0], [%1], 16;" :: "r"(d), "l"(s));
}
#define CP_COMMIT() asm volatile("cp.async.commit_group;" ::: "memory")
#define CP_WAIT0()  asm volatile("cp.async.wait_group 0;" ::: "memory")
#define CP_WAIT1()  asm volatile("cp.async.wait_group 1;" ::: "memory")

__device__ __forceinline__ void ldsm_x4(unsigned& r0, unsigned& r1,
                                        unsigned& r2, unsigned& r3, unsigned addr) {
    asm volatile("ldmatrix.sync.aligned.m8n8.x4.shared.b16 {%0,%1,%2,%3}, [%4];"
                 : "=r"(r0), "=r"(r1), "=r"(r2), "=r"(r3) : "r"(addr));
}
__device__ __forceinline__ void mma_bf16(float* c, const unsigned* a, const unsigned* b) {
    asm volatile("mma.sync.aligned.m16n8k16.row.col.f32.bf16.bf16.f32 "
                 "{%0,%1,%2,%3}, {%4,%5,%6,%7}, {%8,%9}, {%0,%1,%2,%3};"
                 : "+f"(c[0]), "+f"(c[1]), "+f"(c[2]), "+f"(c[3])
                 : "r"(a[0]), "r"(a[1]), "r"(a[2]), "r"(a[3]), "r"(b[0]), "r"(b[1]));
}
__device__ __forceinline__ void bf16split(float v, __nv_bfloat16& h, __nv_bfloat16& l) {
    h = __float2bfloat16(v);
    l = __float2bfloat16(v - __bfloat162float(h));
}
__device__ __forceinline__ unsigned pack2(__nv_bfloat16 a, __nv_bfloat16 b) {
    return ((unsigned)__bfloat16_as_ushort(b) << 16) | __bfloat16_as_ushort(a);
}
__device__ __forceinline__ unsigned pack2f(float a, float b) {
    return pack2(__float2bfloat16(a), __float2bfloat16(b));
}

// ---------------------------------------------------------------------------
// Generic MMA GEMM, SPLIT in {0,1} (1 = hi/lo 3-pass split operands).
//   OUT_MODE 0: fp32 C (+bias)
//   OUT_MODE 1: bf16 hi/lo split C (+bias)
//   OUT_MODE 2: V-projection: stage to smem, coalesced transposed vTh write
//   OUT_MODE 3: single bf16 C (+bias)
// ---------------------------------------------------------------------------
template<int BN, int SPLIT>
__device__ __forceinline__ void mm_load(unsigned dst, int t,
    const char* Ah, const char* Al, const char* Bh, const char* Bl,
    int ldaB, int ldbB, int m0, int n0, int kByte)
{
    constexpr int AOP = 128 * 80, BOP = BN * 80;
    constexpr int NA = 512 * (1 + SPLIT);
    constexpr int TC = NA + BN * 4 * (1 + SPLIT);
#pragma unroll
    for (int u = 0; u < TC / 256; u++) {
        int i = t + u * 256;
        if (i < NA) {
            int half = SPLIT ? (i >> 9) : 0;
            int row = (i >> 2) & 127, c = i & 3;
            const char* s = half ? Al : Ah;
            cpasync16(dst + half * AOP + row * 80 + c * 16,
                      s + (size_t)(m0 + row) * ldaB + kByte + c * 16);
        } else {
            int j = i - NA;
            int half = SPLIT ? (j / (BN * 4)) : 0;
            int row = (j >> 2) % BN, c = j & 3;
            const char* s = half ? Bl : Bh;
            cpasync16(dst + (1 + SPLIT) * AOP + half * BOP + row * 80 + c * 16,
                      s + (size_t)(n0 + row) * ldbB + kByte + c * 16);
        }
    }
}

template<int BN, int OUT_MODE, int SPLIT>
__global__ __launch_bounds__(256, 1)
void mma_gemm(const __nv_bfloat16* __restrict__ Ah, const __nv_bfloat16* __restrict__ Al,
              int lda, long long sA,
              const __nv_bfloat16* __restrict__ Bh, const __nv_bfloat16* __restrict__ Bl,
              int ldb, long long sB,
              const float* __restrict__ bias,
              float* __restrict__ C,
              __nv_bfloat16* __restrict__ Ch, __nv_bfloat16* __restrict__ Cl,
              int ldc, long long sC, int K)
{
    constexpr int AOP = 128 * 80, BOP = BN * 80;
    constexpr int BBASE = (1 + SPLIT) * AOP;
    constexpr int ST = (1 + SPLIT) * (AOP + BOP);
    constexpr int NW = BN / 4;
    constexpr int NI = NW / 8;
    constexpr int NGI = NW / 16;

    extern __shared__ char smem[];
    const unsigned sb = smem_u32(smem);
    const int t = threadIdx.x;
    const int n0 = blockIdx.x * BN, m0 = blockIdx.y * 128, z = blockIdx.z;

    const char* cAh = (const char*)(Ah + (size_t)z * sA);
    const char* cAl = SPLIT ? (const char*)(Al + (size_t)z * sA) : cAh;
    const char* cBh = (const char*)(Bh + (size_t)z * sB);
    const char* cBl = SPLIT ? (const char*)(Bl + (size_t)z * sB) : cBh;
    const int ldaB = lda * 2, ldbB = ldb * 2;

    const int w = t >> 5, lane = t & 31;
    const int wm = (w & 1) * 64, wn = (w >> 1) * NW;
    const int aRowSel = (lane & 7) + ((lane >> 3) & 1) * 8;
    const int aChunk  = (lane >> 4) * 16;
    const int bRowSel = (lane & 7) + (lane >> 4) * 8;
    const int bChunk  = ((lane >> 3) & 1) * 16;

    float acc[4][NI][4];
#pragma unroll
    for (int mi = 0; mi < 4; mi++)
#pragma unroll
        for (int ni = 0; ni < NI; ni++)
#pragma unroll
            for (int r = 0; r < 4; r++) acc[mi][ni][r] = 0.f;

    const int nst = K / 32;
    mm_load<BN, SPLIT>(sb, t, cAh, cAl, cBh, cBl, ldaB, ldbB, m0, n0, 0);
    CP_COMMIT();

    for (int s = 0; s < nst; s++) {
        if (s + 1 < nst) {
            mm_load<BN, SPLIT>(sb + ((s + 1) & 1) * ST, t, cAh, cAl, cBh, cBl,
                               ldaB, ldbB, m0, n0, (s + 1) * 64);
            CP_COMMIT();
            CP_WAIT1();
        } else {
            CP_WAIT0();
        }
        __syncthreads();

        const unsigned base = sb + (s & 1) * ST;
#pragma unroll
        for (int s2 = 0; s2 < 2; s2++) {
            unsigned ah[4][4], al[4][4];
#pragma unroll
            for (int mi = 0; mi < 4; mi++) {
                unsigned ar = base + (wm + mi * 16 + aRowSel) * 80 + s2 * 32 + aChunk;
                ldsm_x4(ah[mi][0], ah[mi][1], ah[mi][2], ah[mi][3], ar);
                if (SPLIT) ldsm_x4(al[mi][0], al[mi][1], al[mi][2], al[mi][3], ar + AOP);
            }
            unsigned bh[NI][2], bl[NI][2];
#pragma unroll
            for (int ngi = 0; ngi < NGI; ngi++) {
                unsigned br = base + BBASE + (wn + ngi * 16 + bRowSel) * 80 + s2 * 32 + bChunk;
                unsigned r0, r1, r2, r3;
                ldsm_x4(r0, r1, r2, r3, br);
                bh[2 * ngi][0] = r0; bh[2 * ngi][1] = r1;
                bh[2 * ngi + 1][0] = r2; bh[2 * ngi + 1][1] = r3;
                if (SPLIT) {
                    ldsm_x4(r0, r1, r2, r3, br + BOP);
                    bl[2 * ngi][0] = r0; bl[2 * ngi][1] = r1;
                    bl[2 * ngi + 1][0] = r2; bl[2 * ngi + 1][1] = r3;
                }
            }
#pragma unroll
            for (int mi = 0; mi < 4; mi++)
#pragma unroll
                for (int ni = 0; ni < NI; ni++) {
                    mma_bf16(acc[mi][ni], ah[mi], bh[ni]);
                    if (SPLIT) {
                        mma_bf16(acc[mi][ni], ah[mi], bl[ni]);
                        mma_bf16(acc[mi][ni], al[mi], bh[ni]);
                    }
                }
        }
        __syncthreads();
    }

    const int g = lane >> 2, tg = lane & 3;

    if (OUT_MODE == 2) {
        float* Ss = (float*)smem;
#pragma unroll
        for (int mi = 0; mi < 4; mi++)
#pragma unroll
            for (int ni = 0; ni < NI; ni++) {
                int col = wn + ni * 8 + 2 * tg;
                float b0 = __ldg(bias + n0 + col), b1 = __ldg(bias + n0 + col + 1);
#pragma unroll
                for (int half = 0; half < 2; half++) {
                    int row = wm + mi * 16 + half * 8 + g;
                    Ss[row * 132 + col]     = acc[mi][ni][2 * half + 0] + b0;
                    Ss[row * 132 + col + 1] = acc[mi][ni][2 * half + 1] + b1;
                }
            }
        __syncthreads();
        const int b = m0 >> 10, l0 = m0 & 1023;
        const int m = lane * 4;
#pragma unroll
        for (int i = 0; i < 16; i++) {
            int n = w * 16 + i;
            float v0 = Ss[(m + 0) * 132 + n];
            float v1 = Ss[(m + 1) * 132 + n];
            float v2 = Ss[(m + 2) * 132 + n];
            float v3 = Ss[(m + 3) * 132 + n];
            size_t ob = ((size_t)(b * 256 + n0 + n)) * 1024 + l0 + m;
            uint2 uh;
            uh.x = pack2f(v0, v1);
            uh.y = pack2f(v2, v3);
            *(uint2*)(Ch + ob) = uh;
        }
        return;
    }

#pragma unroll
    for (int mi = 0; mi < 4; mi++) {
#pragma unroll
        for (int ni = 0; ni < NI; ni++) {
            int gr = m0 + wm + mi * 16 + g;
            int gc = n0 + wn + ni * 8 + 2 * tg;
            float b0 = 0.f, b1 = 0.f;
            if (bias) { b0 = __ldg(bias + gc); b1 = __ldg(bias + gc + 1); }
#pragma unroll
            for (int half = 0; half < 2; half++) {
                size_t idx = (size_t)z * sC + (size_t)(gr + half * 8) * ldc + gc;
                float v0 = acc[mi][ni][2 * half + 0] + b0;
                float v1 = acc[mi][ni][2 * half + 1] + b1;
                if (OUT_MODE == 1) {
                    __nv_bfloat16 h0, l0b, h1, l1b;
                    bf16split(v0, h0, l0b); bf16split(v1, h1, l1b);
                    *(__nv_bfloat162*)(Ch + idx) = __halves2bfloat162(h0, h1);
                    *(__nv_bfloat162*)(Cl + idx) = __halves2bfloat162(l0b, l1b);
                } else if (OUT_MODE == 3) {
                    *(unsigned*)(Ch + idx) = pack2f(v0, v1);
                } else {
                    float2 o; o.x = v0; o.y = v1;
                    *(float2*)(C + idx) = o;
                }
            }
        }
    }
}

// ---------------------------------------------------------------------------
// Fused flash attention v3: S per-warp-m (16 rows), P staged through smem,
// PV re-tiled 2x4 warps (64m x 64n each) — kills V-fragment redundancy.
// Grid (8 m-tiles, 64 b); 256 threads.
// smem: Q 10240 | 2 x (K 10240 + V 81920) | P 128x272 | SC 512 | GZ 512
// ---------------------------------------------------------------------------
#define FA_CBS  92160
#define FA_P    194560
#define FA_SC   229376
#define FA_GZ   229888
#define FA_SMEM 230400

__device__ __forceinline__ void fa_load_q(unsigned sb, int t, const char* gQ)
{
#pragma unroll
    for (int u = 0; u < 2; u++) {
        int i = t + u * 256;
        int row = i >> 2, c = i & 3;
        cpasync16(sb + row * 80 + c * 16, gQ + (size_t)row * 128 + c * 16);
    }
}

__device__ __forceinline__ void fa_load_chunk(unsigned dst, int t,
    const char* gK, const char* gV, int ch)
{
#pragma unroll
    for (int u = 0; u < 2; u++) {     // K: 128 rows x 64B
        int i = t + u * 256;
        int row = i >> 2, c = i & 3;
        cpasync16(dst + row * 80 + c * 16,
                  gK + (size_t)(ch * 128 + row) * 128 + c * 16);
    }
#pragma unroll
    for (int u = 0; u < 16; u++) {    // V: 4 k-groups x 256 n x 64B
        int i = t + u * 256;
        int c = i & 3, n = (i >> 2) & 255, kg = i >> 10;
        cpasync16(dst + 10240 + kg * 20480 + n * 80 + c * 16,
                  gV + (size_t)n * 2048 + ch * 256 + kg * 64 + c * 16);
    }
}

__global__ __launch_bounds__(256, 1)
void fa_kernel(const __nv_bfloat16* __restrict__ qkh,
               const __nv_bfloat16* __restrict__ vTh,
               const __nv_bfloat16* __restrict__ resh, const __nv_bfloat16* __restrict__ resl,
               const float* __restrict__ gammaPtr,
               __nv_bfloat16* __restrict__ atth, __nv_bfloat16* __restrict__ attl)
{
    extern __shared__ char smem[];
    const unsigned sb = smem_u32(smem);
    float* SCf = (float*)(smem + FA_SC);
    float* GZf = (float*)(smem + FA_GZ);
    const unsigned sbP = sb + FA_P;
    const int t = threadIdx.x;
    const int m0 = blockIdx.x * 128, b = blockIdx.y;

    const char* gQ = (const char*)qkh + (size_t)(b * 1024 + m0) * 128;
    const char* gK = (const char*)qkh + (size_t)(b * 1024) * 128 + 64;
    const char* gV = (const char*)vTh + (size_t)(b * 256) * 2048;

    const int w = t >> 5, lane = t & 31;
    const int wm = w * 16;              // S-phase rows
    const int mw = (w >> 2) * 64;       // PV m-group base (0 or 64)
    const int nw = (w & 3) * 64;        // PV n-group base
    const int g = lane >> 2, tg = lane & 3;
    const int aRowSel = (lane & 7) + ((lane >> 3) & 1) * 8;
    const int aChunk  = (lane >> 4) * 16;
    const int bRowSel = (lane & 7) + (lane >> 4) * 8;
    const int bChunk  = ((lane >> 3) & 1) * 16;

    float oacc[4][8][4];    // [mt][nj][r] : rows mw+mt*16+{g,g+8}, cols nw+nj*8+2tg
#pragma unroll
    for (int mt = 0; mt < 4; mt++)
#pragma unroll
        for (int nj = 0; nj < 8; nj++)
#pragma unroll
            for (int r = 0; r < 4; r++) oacc[mt][nj][r] = 0.f;
    float m0r = -1e30f, m1r = -1e30f, z0r = 0.f, z1r = 0.f;

    fa_load_q(sb, t, gQ);
    fa_load_chunk(sb + 10240, t, gK, gV, 0);
    CP_COMMIT();

    for (int ch = 0; ch < 8; ch++) {
        if (ch + 1 < 8) {
            fa_load_chunk(sb + 10240 + ((ch + 1) & 1) * FA_CBS, t, gK, gV, ch + 1);
            CP_COMMIT();
            CP_WAIT1();
        } else {
            CP_WAIT0();
        }
        __syncthreads();

        const unsigned kb = sb + 10240 + (ch & 1) * FA_CBS;

        // ---- S = Q K_chunk^T (single pass), 16m x 128j per warp ----
        float sacc[16][4];
#pragma unroll
        for (int ni = 0; ni < 16; ni++)
#pragma unroll
            for (int r = 0; r < 4; r++) sacc[ni][r] = 0.f;

#pragma unroll
        for (int s2 = 0; s2 < 2; s2++) {
            unsigned qh[4];
            ldsm_x4(qh[0], qh[1], qh[2], qh[3],
                    sb + (wm + aRowSel) * 80 + s2 * 32 + aChunk);
#pragma unroll
            for (int ngi = 0; ngi < 8; ngi++) {
                unsigned br = kb + (ngi * 16 + bRowSel) * 80 + s2 * 32 + bChunk;
                unsigned r0, r1, r2, r3;
                ldsm_x4(r0, r1, r2, r3, br);
                unsigned b0[2] = { r0, r1 }, b1[2] = { r2, r3 };
                mma_bf16(sacc[2 * ngi],     qh, b0);
                mma_bf16(sacc[2 * ngi + 1], qh, b1);
            }
        }

        // ---- online softmax (register + shfl over the 4 tg lanes) ----
        float cm0 = -1e30f, cm1 = -1e30f;
#pragma unroll
        for (int ni = 0; ni < 16; ni++) {
            cm0 = fmaxf(cm0, fmaxf(sacc[ni][0], sacc[ni][1]));
            cm1 = fmaxf(cm1, fmaxf(sacc[ni][2], sacc[ni][3]));
        }
        cm0 = fmaxf(cm0, __shfl_xor_sync(0xffffffffu, cm0, 1));
        cm0 = fmaxf(cm0, __shfl_xor_sync(0xffffffffu, cm0, 2));
        cm1 = fmaxf(cm1, __shfl_xor_sync(0xffffffffu, cm1, 1));
        cm1 = fmaxf(cm1, __shfl_xor_sync(0xffffffffu, cm1, 2));

        float nm0 = fmaxf(m0r, cm0), nm1 = fmaxf(m1r, cm1);
        float sc0 = __expf(m0r - nm0), sc1 = __expf(m1r - nm1);
        float cs0 = 0.f, cs1 = 0.f;
#pragma unroll
        for (int ni = 0; ni < 16; ni++) {
            sacc[ni][0] = __expf(sacc[ni][0] - nm0);
            sacc[ni][1] = __expf(sacc[ni][1] - nm0);
            sacc[ni][2] = __expf(sacc[ni][2] - nm1);
            sacc[ni][3] = __expf(sacc[ni][3] - nm1);
            cs0 += sacc[ni][0] + sacc[ni][1];
            cs1 += sacc[ni][2] + sacc[ni][3];
        }
        cs0 += __shfl_xor_sync(0xffffffffu, cs0, 1);
        cs0 += __shfl_xor_sync(0xffffffffu, cs0, 2);
        cs1 += __shfl_xor_sync(0xffffffffu, cs1, 1);
        cs1 += __shfl_xor_sync(0xffffffffu, cs1, 2);

        z0r = z0r * sc0 + cs0;
        z1r = z1r * sc1 + cs1;
        m0r = nm0; m1r = nm1;

        // ---- stage rescale factors + P (bf16) to smem ----
        if (tg == 0) { SCf[wm + g] = sc0; SCf[wm + g + 8] = sc1; }
#pragma unroll
        for (int ni = 0; ni < 16; ni++) {
            int col2 = (ni * 8 + 2 * tg) * 2;   // byte offset of packed pair
            *(unsigned*)(smem + FA_P + (wm + g) * 272 + col2)     = pack2f(sacc[ni][0], sacc[ni][1]);
            *(unsigned*)(smem + FA_P + (wm + g + 8) * 272 + col2) = pack2f(sacc[ni][2], sacc[ni][3]);
        }
        __syncthreads();

        // ---- rescale O with this chunk's factors (rows mw + mt*16 + g/g+8) ----
#pragma unroll
        for (int mt = 0; mt < 4; mt++) {
            float sa = SCf[mw + mt * 16 + g];
            float sb2 = SCf[mw + mt * 16 + 8 + g];
#pragma unroll
            for (int nj = 0; nj < 8; nj++) {
                oacc[mt][nj][0] *= sa;  oacc[mt][nj][1] *= sa;
                oacc[mt][nj][2] *= sb2; oacc[mt][nj][3] *= sb2;
            }
        }

        // ---- O += P @ V, warp tile 64m x 64n (V + P frags, no redundancy) ----
#pragma unroll
        for (int u = 0; u < 8; u++) {
            unsigned bv[8][2];
            const unsigned vgb = kb + 10240 + (u >> 1) * 20480;
            const int s2v = u & 1;
#pragma unroll
            for (int ngi = 0; ngi < 4; ngi++) {
                unsigned r0, r1, r2, r3;
                ldsm_x4(r0, r1, r2, r3,
                        vgb + (nw + ngi * 16 + bRowSel) * 80 + s2v * 32 + bChunk);
                bv[2 * ngi][0] = r0; bv[2 * ngi][1] = r1;
                bv[2 * ngi + 1][0] = r2; bv[2 * ngi + 1][1] = r3;
            }
#pragma unroll
            for (int mt = 0; mt < 4; mt++) {
                unsigned pa[4];
                ldsm_x4(pa[0], pa[1], pa[2], pa[3],
                        sbP + (mw + mt * 16 + aRowSel) * 272 + u * 32 + aChunk);
#pragma unroll
                for (int nj = 0; nj < 8; nj++)
                    mma_bf16(oacc[mt][nj], pa, bv[nj]);
            }
        }
        __syncthreads();
    }

    // ---- epilogue: att = gamma * O / z + (xah + xal) -> bf16 hi/lo ----
    const float gam = __ldg(gammaPtr);
    if (tg == 0) { GZf[wm + g] = gam / z0r; GZf[wm + g + 8] = gam / z1r; }
    __syncthreads();
#pragma unroll
    for (int mt = 0; mt < 4; mt++) {
        const float gza = GZf[mw + mt * 16 + g];
        const float gzb = GZf[mw + mt * 16 + 8 + g];
        const int grow = b * 1024 + m0 + mw + mt * 16 + g;
#pragma unroll
        for (int nj = 0; nj < 8; nj++) {
            int gc = nw + nj * 8 + 2 * tg;
            size_t i0 = (size_t)grow * 256 + gc;
            size_t i1 = i0 + (size_t)8 * 256;
            __nv_bfloat162 rh0 = *(const __nv_bfloat162*)(resh + i0);
            __nv_bfloat162 rl0 = *(const __nv_bfloat162*)(resl + i0);
            __nv_bfloat162 rh1 = *(const __nv_bfloat162*)(resh + i1);
            __nv_bfloat162 rl1 = *(const __nv_bfloat162*)(resl + i1);
            float v0 = fmaf(gza, oacc[mt][nj][0], __bfloat162float(rh0.x) + __bfloat162float(rl0.x));
            float v1 = fmaf(gza, oacc[mt][nj][1], __bfloat162float(rh0.y) + __bfloat162float(rl0.y));
            float v2 = fmaf(gzb, oacc[mt][nj][2], __bfloat162float(rh1.x) + __bfloat162float(rl1.x));
            float v3 = fmaf(gzb, oacc[mt][nj][3], __bfloat162float(rh1.y) + __bfloat162float(rl1.y));
            __nv_bfloat16 h0, l0, h1, l1;
            bf16split(v0, h0, l0); bf16split(v1, h1, l1);
            *(__nv_bfloat162*)(atth + i0) = __halves2bfloat162(h0, h1);
            *(__nv_bfloat162*)(attl + i0) = __halves2bfloat162(l0, l1);
            bf16split(v2, h0, l0); bf16split(v3, h1, l1);
            *(__nv_bfloat162*)(atth + i1) = __halves2bfloat162(h0, h1);
            *(__nv_bfloat162*)(attl + i1) = __halves2bfloat162(l0, l1);
        }
    }
}

// ---------------------------------------------------------------------------
// SIMT SGEMM (only for tiny pre-linear), B stored [N,K] row-major
// ---------------------------------------------------------------------------
__global__ __launch_bounds__(256)
void sgemm_kernel(const float* __restrict__ A, const float* __restrict__ Bm,
                  const float* __restrict__ bias, float* __restrict__ C,
                  int M, int N, int K, int lda, int ldb, int ldc)
{
    __shared__ float As[8][128];
    __shared__ float Bs[8][128];

    const int tid = threadIdx.x;
    const int m0 = blockIdx.y * 128;
    const int n0 = blockIdx.x * 128;

    const int aRow = tid >> 1;
    const int aK   = (tid & 1) << 2;
    const int tr = (tid >> 4) << 3;
    const int tc = (tid & 15) << 3;

    const bool aOK = (m0 + aRow) < M;
    const bool bOK = (n0 + aRow) < N;
    const float* aPtr = A + (long long)(m0 + aRow) * lda + aK;
    const float* bPtr = Bm + (long long)(n0 + aRow) * ldb + aK;

    float acc[8][8];
#pragma unroll
    for (int i = 0; i < 8; i++)
#pragma unroll
        for (int j = 0; j < 8; j++) acc[i][j] = 0.f;

    float4 aReg = make_float4(0.f, 0.f, 0.f, 0.f);
    float4 bReg = make_float4(0.f, 0.f, 0.f, 0.f);
    if (aOK) aReg = *(const float4*)aPtr;
    if (bOK) bReg = *(const float4*)bPtr;

    for (int k0 = 0; k0 < K; k0 += 8) {
        As[aK + 0][aRow] = aReg.x; As[aK + 1][aRow] = aReg.y;
        As[aK + 2][aRow] = aReg.z; As[aK + 3][aRow] = aReg.w;
        Bs[aK + 0][aRow] = bReg.x; Bs[aK + 1][aRow] = bReg.y;
        Bs[aK + 2][aRow] = bReg.z; Bs[aK + 3][aRow] = bReg.w;
        __syncthreads();

        if (k0 + 8 < K) {
            aReg = make_float4(0.f, 0.f, 0.f, 0.f);
            bReg = make_float4(0.f, 0.f, 0.f, 0.f);
            if (aOK) aReg = *(const float4*)(aPtr + (k0 + 8));
            if (bOK) bReg = *(const float4*)(bPtr + (k0 + 8));
        }

#pragma unroll
        for (int kk = 0; kk < 8; kk++) {
            float ar[8], br[8];
            *(float4*)&ar[0] = *(const float4*)&As[kk][tr];
            *(float4*)&ar[4] = *(const float4*)&As[kk][tr + 4];
            *(float4*)&br[0] = *(const float4*)&Bs[kk][tc];
            *(float4*)&br[4] = *(const float4*)&Bs[kk][tc + 4];
#pragma unroll
            for (int i = 0; i < 8; i++)
#pragma unroll
                for (int j = 0; j < 8; j++)
                    acc[i][j] = fmaf(ar[i], br[j], acc[i][j]);
        }
        __syncthreads();
    }

#pragma unroll
    for (int i = 0; i < 8; i++) {
        int gm = m0 + tr + i;
        if (gm < M) {
#pragma unroll
            for (int j = 0; j < 8; j += 4) {
                int gn = n0 + tc + j;
                if (gn < N) {
                    float4 o;
                    o.x = acc[i][j]; o.y = acc[i][j + 1];
                    o.z = acc[i][j + 2]; o.w = acc[i][j + 3];
                    if (bias) {
                        o.x += __ldg(bias + gn);     o.y += __ldg(bias + gn + 1);
                        o.z += __ldg(bias + gn + 2); o.w += __ldg(bias + gn + 3);
                    }
                    *(float4*)(C + (long long)gm * ldc + gn) = o;
                }
            }
        }
    }
}

// ---------------------------------------------------------------------------
// Weight prep: wq||wk single bf16; wv single bf16; w1 split; merge bq||bk
// ---------------------------------------------------------------------------
__global__ void wprep_kernel(const float* __restrict__ wq, const float* __restrict__ wk,
                             const float* __restrict__ wv, const float* __restrict__ w1,
                             const float* __restrict__ bq, const float* __restrict__ bk,
                             float* __restrict__ bqk,
                             __nv_bfloat16* __restrict__ wqkh,
                             __nv_bfloat16* __restrict__ wvh,
                             __nv_bfloat16* __restrict__ w1h, __nv_bfloat16* __restrict__ w1l)
{
    int i = blockIdx.x * 256 + threadIdx.x;
    if (i < 16384) {
        int n = i >> 8, k = i & 255;
        float v = (n < 32) ? wq[n * 256 + k] : wk[(n - 32) * 256 + k];
        wqkh[i] = __float2bfloat16(v);
    } else if (i < 81920) {
        int j = i - 16384;
        wvh[j] = __float2bfloat16(wv[j]);
    } else if (i < 98304) {
        int j = i - 81920;
        __nv_bfloat16 h, l;
        bf16split(w1[j], h, l);
        w1h[j] = h; w1l[j] = l;
    }
    if (i < 64) bqk[i] = (i < 32) ? bq[i] : bk[i - 32];
}

// ---------------------------------------------------------------------------
// x0 moment stats (8 + 36 vals) per batch; deterministic reductions.
// ---------------------------------------------------------------------------
__global__ __launch_bounds__(256)
void xstats_partial(const float* __restrict__ x0, float* __restrict__ pX)
{
    const int b = blockIdx.x, t = threadIdx.x;
    const int warp = t >> 5, lane = t & 31;
    float a[44];
#pragma unroll
    for (int j = 0; j < 44; j++) a[j] = 0.f;

#pragma unroll
    for (int r = 0; r < 4; r++) {
        int l = t + r * 256;
        float v[CIN];
#pragma unroll
        for (int c = 0; c < CIN; c++)
            v[c] = x0[b * (CIN * LL) + c * LL + l];
#pragma unroll
        for (int c = 0; c < CIN; c++) a[c] += v[c];
        int idx = CIN;
#pragma unroll
        for (int c1 = 0; c1 < CIN; c1++)
#pragma unroll
            for (int c2 = c1; c2 < CIN; c2++)
                a[idx++] = fmaf(v[c1], v[c2], a[idx]);
    }
#pragma unroll
    for (int j = 0; j < 44; j++)
#pragma unroll
        for (int o = 16; o; o >>= 1)
            a[j] += __shfl_xor_sync(0xffffffffu, a[j], o);

    __shared__ float ws[8][44];
    if (lane == 0)
#pragma unroll
        for (int j = 0; j < 44; j++) ws[warp][j] = a[j];
    __syncthreads();
    if (t < 44) {
        float s = ws[0][t];
#pragma unroll
        for (int w = 1; w < 8; w++) s += ws[w][t];
        pX[b * 44 + t] = s;
    }
}

__global__ void xstats_final(const float* __restrict__ pX,
                             const float* __restrict__ w0, const float* __restrict__ b0,
                             const float* __restrict__ g0, const float* __restrict__ be0,
                             float* __restrict__ scale, float* __restrict__ shift)
{
    __shared__ float mom[44];
    __shared__ float mu[CIN];
    __shared__ float cov[CIN][CIN];
    const int t = threadIdx.x;
    if (t < 44) {
        float s = 0.f;
        for (int b = 0; b < 64; b++) s += pX[b * 44 + t];
        mom[t] = s;
    }
    __syncthreads();
    if (t == 0) {
        const float inv = 1.f / 65536.f;
        for (int c = 0; c < CIN; c++) mu[c] = mom[c] * inv;
        int idx = CIN;
        for (int c1 = 0; c1 < CIN; c1++)
            for (int c2 = c1; c2 < CIN; c2++) {
                float cv = mom[idx++] * inv - mu[c1] * mu[c2];
                cov[c1][c2] = cv; cov[c2][c1] = cv;
            }
    }
    __syncthreads();
    float w[CIN];
#pragma unroll
    for (int c = 0; c < CIN; c++) w[c] = w0[t * CIN + c];
    float mean = __ldg(b0 + t);
#pragma unroll
    for (int c = 0; c < CIN; c++) mean = fmaf(w[c], mu[c], mean);
    float var = 0.f;
#pragma unroll
    for (int c1 = 0; c1 < CIN; c1++) {
        float acc = 0.f;
#pragma unroll
        for (int c2 = 0; c2 < CIN; c2++) acc = fmaf(w[c2], cov[c1][c2], acc);
        var = fmaf(w[c1], acc, var);
    }
    float sc = __ldg(g0 + t) * rsqrtf(var + 1e-5f);
    scale[t] = sc;
    shift[t] = __ldg(be0 + t) - mean * sc;
}

// ---------------------------------------------------------------------------
// Fused conv0 + BN0 + ReLU -> xah/xal bf16
// ---------------------------------------------------------------------------
__global__ __launch_bounds__(256)
void conv0_fused(const float* __restrict__ x0, const float* __restrict__ w0,
                 const float* __restrict__ b0,
                 const float* __restrict__ sc0, const float* __restrict__ sh0,
                 __nv_bfloat16* __restrict__ xah, __nv_bfloat16* __restrict__ xal)
{
    __shared__ float ws[C0C * CIN];
    __shared__ float xs[CIN][16];
    const int t = threadIdx.x;
    for (int i = t; i < C0C * CIN; i += 256) ws[i] = w0[i];
    const int g0 = blockIdx.x * 16;
    const int b = g0 >> 10, l0 = g0 & 1023;
    if (t < 128) {
        int c = t >> 4, i = t & 15;
        xs[c][i] = x0[b * (CIN * LL) + c * LL + l0 + i];
    }
    __syncthreads();

    float wreg[CIN];
#pragma unroll
    for (int c = 0; c < CIN; c++) wreg[c] = ws[t * CIN + c];
    const float bb = __ldg(b0 + t);
    const float sc = __ldg(sc0 + t), sh = __ldg(sh0 + t);
#pragma unroll
    for (int i = 0; i < 16; i++) {
        float acc = bb;
#pragma unroll
        for (int c = 0; c < CIN; c++) acc = fmaf(wreg[c], xs[c][i], acc);
        float v = fmaxf(fmaf(acc, sc, sh), 0.f);
        __nv_bfloat16 h, l;
        bf16split(v, h, l);
        size_t o = (size_t)(g0 + i) * C0C + t;
        xah[o] = h; xal[o] = l;
    }
}

// ---------------------------------------------------------------------------
// BN stats (deterministic two-stage) — BN1 only
// ---------------------------------------------------------------------------
__global__ __launch_bounds__(256)
void bnstats_partial(const float* __restrict__ y, int nch,
                     float* __restrict__ pS, float* __restrict__ pQ)
{
    const int chunk = blockIdx.x;
    const int group = blockIdx.y;
    const int t = threadIdx.x;
    const int warp = t >> 5, lane = t & 31;
    const int ch = group * 32 + lane;
    const long long base = (long long)chunk * 1024;

    float s = 0.f, q = 0.f;
    for (int r = warp; r < 1024; r += 8) {
        float v = y[(base + r) * nch + ch];
        s += v; q = fmaf(v, v, q);
    }
    __shared__ float ss[8][32], sq[8][32];
    ss[warp][lane] = s; sq[warp][lane] = q;
    __syncthreads();
    if (warp == 0) {
        float S = ss[0][lane], Q = sq[0][lane];
#pragma unroll
        for (int w = 1; w < 8; w++) { S += ss[w][lane]; Q += sq[w][lane]; }
        pS[ch * 64 + chunk] = S;
        pQ[ch * 64 + chunk] = Q;
    }
}

__global__ void bnfinalize(const float* __restrict__ pS, const float* __restrict__ pQ,
                           const float* __restrict__ g, const float* __restrict__ be,
                           float* __restrict__ scale, float* __restrict__ shift, int nch)
{
    int ch = blockIdx.x * blockDim.x + threadIdx.x;
    if (ch >= nch) return;
    float s0 = 0.f, s1 = 0.f, s2 = 0.f, s3 = 0.f;
    float q0 = 0.f, q1 = 0.f, q2 = 0.f, q3 = 0.f;
#pragma unroll
    for (int i = 0; i < 64; i += 4) {
        s0 += pS[ch * 64 + i];     q0 += pQ[ch * 64 + i];
        s1 += pS[ch * 64 + i + 1]; q1 += pQ[ch * 64 + i + 1];
        s2 += pS[ch * 64 + i + 2]; q2 += pQ[ch * 64 + i + 2];
        s3 += pS[ch * 64 + i + 3]; q3 += pQ[ch * 64 + i + 3];
    }
    float s = (s0 + s1) + (s2 + s3);
    float q = (q0 + q1) + (q2 + q3);
    const float inv = 1.f / 65536.f;
    float mean = s * inv;
    float var = q * inv - mean * mean;
    float sc = __ldg(g + ch) * rsqrtf(var + 1e-5f);
    scale[ch] = sc;
    shift[ch] = __ldg(be + ch) - mean * sc;
}

// ---------------------------------------------------------------------------
// Final: out[b][cin][l] = b_out[cin] + sum_f w_out[cin][f] * relu(bn1(x1[g][f]))
// ---------------------------------------------------------------------------
__global__ __launch_bounds__(256)
void final_kernel(const float* __restrict__ x1,
                  const float* __restrict__ scale1, const float* __restrict__ shift1,
                  const float* __restrict__ w_out, const float* __restrict__ b_out,
                  float* __restrict__ out)
{
    __shared__ float xs[32][65];
    __shared__ float wsh[8][64];
    const int t = threadIdx.x;
    const int g0 = blockIdx.x * 32;

    for (int i = t; i < 32 * 64; i += 256) {
        int pos = i >> 6, f = i & 63;
        float v = x1[(size_t)(g0 + pos) * FFC + f];
        v = fmaf(v, __ldg(scale1 + f), __ldg(shift1 + f));
        xs[pos][f] = fmaxf(v, 0.f);
    }
    for (int i = t; i < 8 * 64; i += 256) wsh[i >> 6][i & 63] = w_out[i];
    __syncthreads();

    const int pos = t & 31, cin = t >> 5;
    float acc = __ldg(b_out + cin);
#pragma unroll
    for (int f = 0; f < 64; f++) acc = fmaf(wsh[cin][f], xs[pos][f], acc);

    const int b = g0 >> 10, l0 = g0 & 1023;
    out[b * (CIN * LL) + cin * LL + l0 + pos] = acc;
}

// ---------------------------------------------------------------------------
// Host launcher (graph-capturable: kernel launches only)
// ---------------------------------------------------------------------------
extern "C" void kernel_launch(void* const* d_in, const int* in_sizes, int n_in,
                              void* d_out, int out_size)
{
    const float* z     = (const float*)d_in[0];
    const float* w_pre = (const float*)d_in[1];
    const float* b_pre = (const float*)d_in[2];
    const float* w0    = (const float*)d_in[3];
    const float* b0    = (const float*)d_in[4];
    const float* g0    = (const float*)d_in[5];
    const float* be0   = (const float*)d_in[6];
    const float* wq    = (const float*)d_in[7];
    const float* bq    = (const float*)d_in[8];
    const float* wk    = (const float*)d_in[9];
    const float* bk    = (const float*)d_in[10];
    const float* wv    = (const float*)d_in[11];
    const float* bv    = (const float*)d_in[12];
    const float* gamma = (const float*)d_in[13];
    const float* w1    = (const float*)d_in[14];
    const float* b1    = (const float*)d_in[15];
    const float* g1    = (const float*)d_in[16];
    const float* be1   = (const float*)d_in[17];
    const float* w_out = (const float*)d_in[18];
    const float* b_out = (const float*)d_in[19];
    float* out = (float*)d_out;

    float *x0, *x1, *pS, *pQ, *sc0, *sh0, *sc1, *sh1, *bqk;
    __nv_bfloat16 *xah, *xal, *qkh, *vTh, *atth, *attl;
    __nv_bfloat16 *wqkh, *wvh, *w1h, *w1l;
    cudaGetSymbolAddress((void**)&x0,   g_x0);
    cudaGetSymbolAddress((void**)&xah,  g_xah);
    cudaGetSymbolAddress((void**)&xal,  g_xal);
    cudaGetSymbolAddress((void**)&qkh,  g_qkh);
    cudaGetSymbolAddress((void**)&vTh,  g_vTh);
    cudaGetSymbolAddress((void**)&atth, g_atth);
    cudaGetSymbolAddress((void**)&attl, g_attl);
    cudaGetSymbolAddress((void**)&x1,   g_x1);
    cudaGetSymbolAddress((void**)&pS,   g_pS);
    cudaGetSymbolAddress((void**)&pQ,   g_pQ);
    cudaGetSymbolAddress((void**)&sc0,  g_scale0);
    cudaGetSymbolAddress((void**)&sh0,  g_shift0);
    cudaGetSymbolAddress((void**)&sc1,  g_scale1);
    cudaGetSymbolAddress((void**)&sh1,  g_shift1);
    cudaGetSymbolAddress((void**)&wqkh, g_wqkh);
    cudaGetSymbolAddress((void**)&wvh,  g_wvh);
    cudaGetSymbolAddress((void**)&w1h,  g_w1h);
    cudaGetSymbolAddress((void**)&w1l,  g_w1l);
    cudaGetSymbolAddress((void**)&bqk,  g_bqk);

    const int ST_QK   = 2 * (128 * 80 + 64 * 80);           // 30720 (SPLIT=0)
    const int ST_VP   = 67584;                              // max(2*20480, Ss 128*132*4)
    const int ST_C1   = 2 * (2 * 128 * 80 + 2 * 64 * 80);   // 61440 (SPLIT=1)
    cudaFuncSetAttribute(fa_kernel, cudaFuncAttributeMaxDynamicSharedMemorySize, FA_SMEM);
    cudaFuncSetAttribute(mma_gemm<64, 3, 0>,  cudaFuncAttributeMaxDynamicSharedMemorySize, ST_QK);
    cudaFuncSetAttribute(mma_gemm<128, 2, 0>, cudaFuncAttributeMaxDynamicSharedMemorySize, ST_VP);
    cudaFuncSetAttribute(mma_gemm<64, 0, 1>,  cudaFuncAttributeMaxDynamicSharedMemorySize, ST_C1);

    // 1) pre-linear: x0 = z @ w_pre^T + b_pre   [64 x 8192], K=128
    sgemm_kernel<<<dim3(8192 / 128, 1, 1), 256>>>(
        z, w_pre, b_pre, x0, NB, CIN * LL, ZD, ZD, ZD, CIN * LL);

    // 2) weight prep (independent)
    wprep_kernel<<<384, 256>>>(wq, wk, wv, w1, bq, bk, bqk,
                               wqkh, wvh, w1h, w1l);

    // 3) BN0 via x0 moments (2 MB) -> analytic scale/shift
    xstats_partial<<<64, 256>>>(x0, pS);
    xstats_final<<<1, 256>>>(pS, w0, b0, g0, be0, sc0, sh0);

    // 4) fused conv0 + BN0 + ReLU -> xah/xal bf16
    conv0_fused<<<GG / 16, 256>>>(x0, w0, b0, sc0, sh0, xah, xal);

    // 5) Q+K projection (single bf16 in/out): [g][64], K=256
    mma_gemm<64, 3, 0><<<dim3(1, GG / 128, 1), 256, ST_QK>>>(
        xah, nullptr, C0C, 0, wqkh, nullptr, C0C, 0, bqk,
        nullptr, qkh, nullptr, 64, 0, C0C);

    // 6) V projection (single bf16 in) with fused transpose -> vTh, K=256
    mma_gemm<128, 2, 0><<<dim3(2, GG / 128, 1), 256, ST_VP>>>(
        xah, nullptr, C0C, 0, wvh, nullptr, C0C, 0, bv,
        nullptr, vTh, nullptr, 0, 0, C0C);

    // 7) fused flash attention v3 (P-staged, n-split PV): att -> bf16 hi/lo
    fa_kernel<<<dim3(8, NB), 256, FA_SMEM>>>(qkh, vTh, xah, xal,
                                             gamma, atth, attl);

    // 8) conv1 (split operands): x1 = att @ w1^T + b1  [g][64], K=256
    mma_gemm<64, 0, 1><<<dim3(1, GG / 128, 1), 256, ST_C1>>>(
        atth, attl, C0C, 0, w1h, w1l, C0C, 0, b1,
        x1, nullptr, nullptr, FFC, 0, C0C);

    // 9) BN1 stats
    bnstats_partial<<<dim3(64, FFC / 32), 256>>>(x1, FFC, pS, pQ);
    bnfinalize<<<1, 64>>>(pS, pQ, g1, be1, sc1, sh1, FFC);

    // 10) fused BN1 + relu + w_out conv -> out [b][8][1024]
    final_kernel<<<GG / 32, 256>>>(x1, sc1, sh1, w_out, b_out, out);

    (void)in_sizes; (void)n_in; (void)out_size;
}

// round 15
// speedup vs baseline: 1.0890x; 1.0890x over previous
#include <cuda_runtime.h>
#include <cuda_bf16.h>

// ---------------------------------------------------------------------------
// Problem constants
// ---------------------------------------------------------------------------
#define NB    64          // batch
#define ZD    128         // latent dim
#define CIN   8
#define LL    1024        // W*H
#define C0C   256         // attention channels
#define CQKC  32
#define FFC   64          // filters
#define GG    65536       // NB * LL (total positions)

// ---------------------------------------------------------------------------
// Device scratch (allocation-free rule: __device__ globals)
// ---------------------------------------------------------------------------
__device__ __align__(16) float g_x0 [NB * CIN * LL];              //  2 MB
__device__ __align__(16) __nv_bfloat16 g_xah[(size_t)GG * C0C];   // 32 MB
__device__ __align__(16) __nv_bfloat16 g_xal[(size_t)GG * C0C];   // 32 MB
__device__ __align__(16) __nv_bfloat16 g_qkh[(size_t)GG * 64];    //  8 MB [g][q32|k32]
__device__ __align__(16) __nv_bfloat16 g_vTh[(size_t)NB * C0C * LL]; // 32 MB V^T bf16
__device__ __align__(16) __nv_bfloat16 g_atth[(size_t)GG * C0C];  // 32 MB att hi
__device__ __align__(16) __nv_bfloat16 g_attl[(size_t)GG * C0C];  // 32 MB att lo
__device__ __align__(16) float g_x1 [(size_t)GG * FFC];           // 16 MB
// weights
__device__ __align__(16) __nv_bfloat16 g_wqkh[64 * C0C];
__device__ __align__(16) __nv_bfloat16 g_wvh [C0C * C0C];
__device__ __align__(16) __nv_bfloat16 g_w1h [FFC * C0C], g_w1l [FFC * C0C];
__device__ __align__(16) float g_bqk[64];
__device__ float g_pS[C0C * 64];           // reused: x0 moment partials [64][44]
__device__ float g_pQ[C0C * 64];
__device__ __align__(16) float g_scale0[C0C], g_shift0[C0C];
__device__ __align__(16) float g_scale1[FFC], g_shift1[FFC];

// ---------------------------------------------------------------------------
// PTX helpers (sm_80-level only — harness ptxas targets plain sm_100)
// ---------------------------------------------------------------------------
__device__ __forceinline__ unsigned smem_u32(const void* p) {
    unsigned a;
    asm("{ .reg .u64 t; cvta.to.shared.u64 t, %1; cvt.u32.u64 %0, t; }" : "=r"(a) : "l"(p));
    return a;
}
__device__ __forceinline__ void cpasync16(unsigned d, const void* s) {
    asm volatile("cp.async.cg.shared.global [%0], [%1], 16;" :: "r"(d), "l"(s));
}
#define CP_COMMIT() asm volatile("cp.async.commit_group;" ::: "memory")
#define CP_WAIT0()  asm volatile("cp.async.wait_group 0;" ::: "memory")
#define CP_WAIT1()  asm volatile("cp.async.wait_group 1;" ::: "memory")

__device__ __forceinline__ void ldsm_x4(unsigned& r0, unsigned& r1,
                                        unsigned& r2, unsigned& r3, unsigned addr) {
    asm volatile("ldmatrix.sync.aligned.m8n8.x4.shared.b16 {%0,%1,%2,%3}, [%4];"
                 : "=r"(r0), "=r"(r1), "=r"(r2), "=r"(r3) : "r"(addr));
}
__device__ __forceinline__ void mma_bf16(float* c, const unsigned* a, const unsigned* b) {
    asm volatile("mma.sync.aligned.m16n8k16.row.col.f32.bf16.bf16.f32 "
                 "{%0,%1,%2,%3}, {%4,%5,%6,%7}, {%8,%9}, {%0,%1,%2,%3};"
                 : "+f"(c[0]), "+f"(c[1]), "+f"(c[2]), "+f"(c[3])
                 : "r"(a[0]), "r"(a[1]), "r"(a[2]), "r"(a[3]), "r"(b[0]), "r"(b[1]));
}
__device__ __forceinline__ void bf16split(float v, __nv_bfloat16& h, __nv_bfloat16& l) {
    h = __float2bfloat16(v);
    l = __float2bfloat16(v - __bfloat162float(h));
}
__device__ __forceinline__ unsigned pack2(__nv_bfloat16 a, __nv_bfloat16 b) {
    return ((unsigned)__bfloat16_as_ushort(b) << 16) | __bfloat16_as_ushort(a);
}
__device__ __forceinline__ unsigned pack2f(float a, float b) {
    return pack2(__float2bfloat16(a), __float2bfloat16(b));
}

// ---------------------------------------------------------------------------
// Generic MMA GEMM, SPLIT in {0,1} (1 = hi/lo 3-pass split operands).
//   OUT_MODE 0: fp32 C (+bias)
//   OUT_MODE 1: bf16 hi/lo split C (+bias)
//   OUT_MODE 2: V-projection: stage to smem, coalesced transposed vTh write
//   OUT_MODE 3: single bf16 C (+bias)
// ---------------------------------------------------------------------------
template<int BN, int SPLIT>
__device__ __forceinline__ void mm_load(unsigned dst, int t,
    const char* Ah, const char* Al, const char* Bh, const char* Bl,
    int ldaB, int ldbB, int m0, int n0, int kByte)
{
    constexpr int AOP = 128 * 80, BOP = BN * 80;
    constexpr int NA = 512 * (1 + SPLIT);
    constexpr int TC = NA + BN * 4 * (1 + SPLIT);
#pragma unroll
    for (int u = 0; u < TC / 256; u++) {
        int i = t + u * 256;
        if (i < NA) {
            int half = SPLIT ? (i >> 9) : 0;
            int row = (i >> 2) & 127, c = i & 3;
            const char* s = half ? Al : Ah;
            cpasync16(dst + half * AOP + row * 80 + c * 16,
                      s + (size_t)(m0 + row) * ldaB + kByte + c * 16);
        } else {
            int j = i - NA;
            int half = SPLIT ? (j / (BN * 4)) : 0;
            int row = (j >> 2) % BN, c = j & 3;
            const char* s = half ? Bl : Bh;
            cpasync16(dst + (1 + SPLIT) * AOP + half * BOP + row * 80 + c * 16,
                      s + (size_t)(n0 + row) * ldbB + kByte + c * 16);
        }
    }
}

template<int BN, int OUT_MODE, int SPLIT>
__global__ __launch_bounds__(256, 1)
void mma_gemm(const __nv_bfloat16* __restrict__ Ah, const __nv_bfloat16* __restrict__ Al,
              int lda, long long sA,
              const __nv_bfloat16* __restrict__ Bh, const __nv_bfloat16* __restrict__ Bl,
              int ldb, long long sB,
              const float* __restrict__ bias,
              float* __restrict__ C,
              __nv_bfloat16* __restrict__ Ch, __nv_bfloat16* __restrict__ Cl,
              int ldc, long long sC, int K)
{
    constexpr int AOP = 128 * 80, BOP = BN * 80;
    constexpr int BBASE = (1 + SPLIT) * AOP;
    constexpr int ST = (1 + SPLIT) * (AOP + BOP);
    constexpr int NW = BN / 4;
    constexpr int NI = NW / 8;
    constexpr int NGI = NW / 16;

    extern __shared__ char smem[];
    const unsigned sb = smem_u32(smem);
    const int t = threadIdx.x;
    const int n0 = blockIdx.x * BN, m0 = blockIdx.y * 128, z = blockIdx.z;

    const char* cAh = (const char*)(Ah + (size_t)z * sA);
    const char* cAl = SPLIT ? (const char*)(Al + (size_t)z * sA) : cAh;
    const char* cBh = (const char*)(Bh + (size_t)z * sB);
    const char* cBl = SPLIT ? (const char*)(Bl + (size_t)z * sB) : cBh;
    const int ldaB = lda * 2, ldbB = ldb * 2;

    const int w = t >> 5, lane = t & 31;
    const int wm = (w & 1) * 64, wn = (w >> 1) * NW;
    const int aRowSel = (lane & 7) + ((lane >> 3) & 1) * 8;
    const int aChunk  = (lane >> 4) * 16;
    const int bRowSel = (lane & 7) + (lane >> 4) * 8;
    const int bChunk  = ((lane >> 3) & 1) * 16;

    float acc[4][NI][4];
#pragma unroll
    for (int mi = 0; mi < 4; mi++)
#pragma unroll
        for (int ni = 0; ni < NI; ni++)
#pragma unroll
            for (int r = 0; r < 4; r++) acc[mi][ni][r] = 0.f;

    const int nst = K / 32;
    mm_load<BN, SPLIT>(sb, t, cAh, cAl, cBh, cBl, ldaB, ldbB, m0, n0, 0);
    CP_COMMIT();

    for (int s = 0; s < nst; s++) {
        if (s + 1 < nst) {
            mm_load<BN, SPLIT>(sb + ((s + 1) & 1) * ST, t, cAh, cAl, cBh, cBl,
                               ldaB, ldbB, m0, n0, (s + 1) * 64);
            CP_COMMIT();
            CP_WAIT1();
        } else {
            CP_WAIT0();
        }
        __syncthreads();

        const unsigned base = sb + (s & 1) * ST;
#pragma unroll
        for (int s2 = 0; s2 < 2; s2++) {
            unsigned ah[4][4], al[4][4];
#pragma unroll
            for (int mi = 0; mi < 4; mi++) {
                unsigned ar = base + (wm + mi * 16 + aRowSel) * 80 + s2 * 32 + aChunk;
                ldsm_x4(ah[mi][0], ah[mi][1], ah[mi][2], ah[mi][3], ar);
                if (SPLIT) ldsm_x4(al[mi][0], al[mi][1], al[mi][2], al[mi][3], ar + AOP);
            }
            unsigned bh[NI][2], bl[NI][2];
#pragma unroll
            for (int ngi = 0; ngi < NGI; ngi++) {
                unsigned br = base + BBASE + (wn + ngi * 16 + bRowSel) * 80 + s2 * 32 + bChunk;
                unsigned r0, r1, r2, r3;
                ldsm_x4(r0, r1, r2, r3, br);
                bh[2 * ngi][0] = r0; bh[2 * ngi][1] = r1;
                bh[2 * ngi + 1][0] = r2; bh[2 * ngi + 1][1] = r3;
                if (SPLIT) {
                    ldsm_x4(r0, r1, r2, r3, br + BOP);
                    bl[2 * ngi][0] = r0; bl[2 * ngi][1] = r1;
                    bl[2 * ngi + 1][0] = r2; bl[2 * ngi + 1][1] = r3;
                }
            }
#pragma unroll
            for (int mi = 0; mi < 4; mi++)
#pragma unroll
                for (int ni = 0; ni < NI; ni++) {
                    mma_bf16(acc[mi][ni], ah[mi], bh[ni]);
                    if (SPLIT) {
                        mma_bf16(acc[mi][ni], ah[mi], bl[ni]);
                        mma_bf16(acc[mi][ni], al[mi], bh[ni]);
                    }
                }
        }
        __syncthreads();
    }

    const int g = lane >> 2, tg = lane & 3;

    if (OUT_MODE == 2) {
        float* Ss = (float*)smem;
#pragma unroll
        for (int mi = 0; mi < 4; mi++)
#pragma unroll
            for (int ni = 0; ni < NI; ni++) {
                int col = wn + ni * 8 + 2 * tg;
                float b0 = __ldg(bias + n0 + col), b1 = __ldg(bias + n0 + col + 1);
#pragma unroll
                for (int half = 0; half < 2; half++) {
                    int row = wm + mi * 16 + half * 8 + g;
                    Ss[row * 132 + col]     = acc[mi][ni][2 * half + 0] + b0;
                    Ss[row * 132 + col + 1] = acc[mi][ni][2 * half + 1] + b1;
                }
            }
        __syncthreads();
        const int b = m0 >> 10, l0 = m0 & 1023;
        const int m = lane * 4;
#pragma unroll
        for (int i = 0; i < 16; i++) {
            int n = w * 16 + i;
            float v0 = Ss[(m + 0) * 132 + n];
            float v1 = Ss[(m + 1) * 132 + n];
            float v2 = Ss[(m + 2) * 132 + n];
            float v3 = Ss[(m + 3) * 132 + n];
            size_t ob = ((size_t)(b * 256 + n0 + n)) * 1024 + l0 + m;
            uint2 uh;
            uh.x = pack2f(v0, v1);
            uh.y = pack2f(v2, v3);
            *(uint2*)(Ch + ob) = uh;
        }
        return;
    }

#pragma unroll
    for (int mi = 0; mi < 4; mi++) {
#pragma unroll
        for (int ni = 0; ni < NI; ni++) {
            int gr = m0 + wm + mi * 16 + g;
            int gc = n0 + wn + ni * 8 + 2 * tg;
            float b0 = 0.f, b1 = 0.f;
            if (bias) { b0 = __ldg(bias + gc); b1 = __ldg(bias + gc + 1); }
#pragma unroll
            for (int half = 0; half < 2; half++) {
                size_t idx = (size_t)z * sC + (size_t)(gr + half * 8) * ldc + gc;
                float v0 = acc[mi][ni][2 * half + 0] + b0;
                float v1 = acc[mi][ni][2 * half + 1] + b1;
                if (OUT_MODE == 1) {
                    __nv_bfloat16 h0, l0b, h1, l1b;
                    bf16split(v0, h0, l0b); bf16split(v1, h1, l1b);
                    *(__nv_bfloat162*)(Ch + idx) = __halves2bfloat162(h0, h1);
                    *(__nv_bfloat162*)(Cl + idx) = __halves2bfloat162(l0b, l1b);
                } else if (OUT_MODE == 3) {
                    *(unsigned*)(Ch + idx) = pack2f(v0, v1);
                } else {
                    float2 o; o.x = v0; o.y = v1;
                    *(float2*)(C + idx) = o;
                }
            }
        }
    }
}

// ---------------------------------------------------------------------------
// Fused flash attention (full 256-ch per CTA, register-direct P — the R13
// 391us configuration): att = gamma*softmax(QK^T)V + xa.
// Grid (8 m-tiles, 64 b); 256 threads, 8 warps of 16 m-rows.
// smem: Q 10240 | 2 chunk buffers x (K 10240 + V 4x20480) = 194560 B.
// ---------------------------------------------------------------------------
#define FA_CBS  92160
#define FA_SMEM 194560

__device__ __forceinline__ void fa_load_q(unsigned sb, int t, const char* gQ)
{
#pragma unroll
    for (int u = 0; u < 2; u++) {
        int i = t + u * 256;
        int row = i >> 2, c = i & 3;
        cpasync16(sb + row * 80 + c * 16, gQ + (size_t)row * 128 + c * 16);
    }
}

__device__ __forceinline__ void fa_load_chunk(unsigned dst, int t,
    const char* gK, const char* gV, int ch)
{
#pragma unroll
    for (int u = 0; u < 2; u++) {     // K: 128 rows x 64B
        int i = t + u * 256;
        int row = i >> 2, c = i & 3;
        cpasync16(dst + row * 80 + c * 16,
                  gK + (size_t)(ch * 128 + row) * 128 + c * 16);
    }
#pragma unroll
    for (int u = 0; u < 16; u++) {    // V: 4 k-groups x 256 n x 64B
        int i = t + u * 256;
        int c = i & 3, n = (i >> 2) & 255, kg = i >> 10;
        cpasync16(dst + 10240 + kg * 20480 + n * 80 + c * 16,
                  gV + (size_t)n * 2048 + ch * 256 + kg * 64 + c * 16);
    }
}

__global__ __launch_bounds__(256, 1)
void fa_kernel(const __nv_bfloat16* __restrict__ qkh,
               const __nv_bfloat16* __restrict__ vTh,
               const __nv_bfloat16* __restrict__ resh, const __nv_bfloat16* __restrict__ resl,
               const float* __restrict__ gammaPtr,
               __nv_bfloat16* __restrict__ atth, __nv_bfloat16* __restrict__ attl)
{
    extern __shared__ char smem[];
    const unsigned sb = smem_u32(smem);
    const int t = threadIdx.x;
    const int m0 = blockIdx.x * 128, b = blockIdx.y;

    const char* gQ = (const char*)qkh + (size_t)(b * 1024 + m0) * 128;
    const char* gK = (const char*)qkh + (size_t)(b * 1024) * 128 + 64;
    const char* gV = (const char*)vTh + (size_t)(b * 256) * 2048;

    const int w = t >> 5, lane = t & 31;
    const int wm = w * 16;
    const int g = lane >> 2, tg = lane & 3;
    const int aRowSel = (lane & 7) + ((lane >> 3) & 1) * 8;
    const int aChunk  = (lane >> 4) * 16;
    const int bRowSel = (lane & 7) + (lane >> 4) * 8;
    const int bChunk  = ((lane >> 3) & 1) * 16;

    float oacc[32][4];
#pragma unroll
    for (int ni = 0; ni < 32; ni++)
#pragma unroll
        for (int r = 0; r < 4; r++) oacc[ni][r] = 0.f;
    float m0r = -1e30f, m1r = -1e30f, z0r = 0.f, z1r = 0.f;

    fa_load_q(sb, t, gQ);
    fa_load_chunk(sb + 10240, t, gK, gV, 0);
    CP_COMMIT();

    for (int ch = 0; ch < 8; ch++) {
        if (ch + 1 < 8) {
            fa_load_chunk(sb + 10240 + ((ch + 1) & 1) * FA_CBS, t, gK, gV, ch + 1);
            CP_COMMIT();
            CP_WAIT1();
        } else {
            CP_WAIT0();
        }
        __syncthreads();

        const unsigned kb = sb + 10240 + (ch & 1) * FA_CBS;

        // ---- S = Q K_chunk^T (single pass), 16m x 128j per warp ----
        float sacc[16][4];
#pragma unroll
        for (int ni = 0; ni < 16; ni++)
#pragma unroll
            for (int r = 0; r < 4; r++) sacc[ni][r] = 0.f;

#pragma unroll
        for (int s2 = 0; s2 < 2; s2++) {
            unsigned qh[4];
            ldsm_x4(qh[0], qh[1], qh[2], qh[3],
                    sb + (wm + aRowSel) * 80 + s2 * 32 + aChunk);
#pragma unroll
            for (int ngi = 0; ngi < 8; ngi++) {
                unsigned br = kb + (ngi * 16 + bRowSel) * 80 + s2 * 32 + bChunk;
                unsigned r0, r1, r2, r3;
                ldsm_x4(r0, r1, r2, r3, br);
                unsigned b0[2] = { r0, r1 }, b1[2] = { r2, r3 };
                mma_bf16(sacc[2 * ngi],     qh, b0);
                mma_bf16(sacc[2 * ngi + 1], qh, b1);
            }
        }

        // ---- online softmax (register + shfl over the 4 tg lanes) ----
        float cm0 = -1e30f, cm1 = -1e30f;
#pragma unroll
        for (int ni = 0; ni < 16; ni++) {
            cm0 = fmaxf(cm0, fmaxf(sacc[ni][0], sacc[ni][1]));
            cm1 = fmaxf(cm1, fmaxf(sacc[ni][2], sacc[ni][3]));
        }
        cm0 = fmaxf(cm0, __shfl_xor_sync(0xffffffffu, cm0, 1));
        cm0 = fmaxf(cm0, __shfl_xor_sync(0xffffffffu, cm0, 2));
        cm1 = fmaxf(cm1, __shfl_xor_sync(0xffffffffu, cm1, 1));
        cm1 = fmaxf(cm1, __shfl_xor_sync(0xffffffffu, cm1, 2));

        float nm0 = fmaxf(m0r, cm0), nm1 = fmaxf(m1r, cm1);
        float sc0 = __expf(m0r - nm0), sc1 = __expf(m1r - nm1);
        float cs0 = 0.f, cs1 = 0.f;
#pragma unroll
        for (int ni = 0; ni < 16; ni++) {
            sacc[ni][0] = __expf(sacc[ni][0] - nm0);
            sacc[ni][1] = __expf(sacc[ni][1] - nm0);
            sacc[ni][2] = __expf(sacc[ni][2] - nm1);
            sacc[ni][3] = __expf(sacc[ni][3] - nm1);
            cs0 += sacc[ni][0] + sacc[ni][1];
            cs1 += sacc[ni][2] + sacc[ni][3];
        }
        cs0 += __shfl_xor_sync(0xffffffffu, cs0, 1);
        cs0 += __shfl_xor_sync(0xffffffffu, cs0, 2);
        cs1 += __shfl_xor_sync(0xffffffffu, cs1, 1);
        cs1 += __shfl_xor_sync(0xffffffffu, cs1, 2);

        z0r = z0r * sc0 + cs0;
        z1r = z1r * sc1 + cs1;
        m0r = nm0; m1r = nm1;
#pragma unroll
        for (int ni = 0; ni < 32; ni++) {
            oacc[ni][0] *= sc0; oacc[ni][1] *= sc0;
            oacc[ni][2] *= sc1; oacc[ni][3] *= sc1;
        }

        // ---- O += P_chunk @ V_chunk (full 256 n; P from C-frag, bf16) ----
#pragma unroll
        for (int u = 0; u < 8; u++) {
            unsigned pa[4];
            pa[0] = pack2f(sacc[2 * u][0],     sacc[2 * u][1]);
            pa[1] = pack2f(sacc[2 * u][2],     sacc[2 * u][3]);
            pa[2] = pack2f(sacc[2 * u + 1][0], sacc[2 * u + 1][1]);
            pa[3] = pack2f(sacc[2 * u + 1][2], sacc[2 * u + 1][3]);
            const unsigned vgb = kb + 10240 + (u >> 1) * 20480;
            const int s2v = u & 1;
#pragma unroll
            for (int ngi = 0; ngi < 16; ngi++) {
                unsigned br = vgb + (ngi * 16 + bRowSel) * 80 + s2v * 32 + bChunk;
                unsigned r0, r1, r2, r3;
                ldsm_x4(r0, r1, r2, r3, br);
                unsigned bv0[2] = { r0, r1 }, bv1[2] = { r2, r3 };
                mma_bf16(oacc[2 * ngi],     pa, bv0);
                mma_bf16(oacc[2 * ngi + 1], pa, bv1);
            }
        }
        __syncthreads();
    }

    // ---- epilogue: att = gamma * O / z + (xah + xal) -> bf16 hi/lo ----
    const float gam = __ldg(gammaPtr);
    const float gz0 = gam / z0r, gz1 = gam / z1r;
    const int gr0 = b * 1024 + m0 + wm + g;
#pragma unroll
    for (int ni = 0; ni < 32; ni++) {
        int gc = ni * 8 + 2 * tg;
        size_t i0 = (size_t)gr0 * 256 + gc;
        size_t i1 = i0 + (size_t)8 * 256;
        __nv_bfloat162 rh0 = *(const __nv_bfloat162*)(resh + i0);
        __nv_bfloat162 rl0 = *(const __nv_bfloat162*)(resl + i0);
        __nv_bfloat162 rh1 = *(const __nv_bfloat162*)(resh + i1);
        __nv_bfloat162 rl1 = *(const __nv_bfloat162*)(resl + i1);
        float v0 = fmaf(gz0, oacc[ni][0], __bfloat162float(rh0.x) + __bfloat162float(rl0.x));
        float v1 = fmaf(gz0, oacc[ni][1], __bfloat162float(rh0.y) + __bfloat162float(rl0.y));
        float v2 = fmaf(gz1, oacc[ni][2], __bfloat162float(rh1.x) + __bfloat162float(rl1.x));
        float v3 = fmaf(gz1, oacc[ni][3], __bfloat162float(rh1.y) + __bfloat162float(rl1.y));
        __nv_bfloat16 h0, l0, h1, l1;
        bf16split(v0, h0, l0); bf16split(v1, h1, l1);
        *(__nv_bfloat162*)(atth + i0) = __halves2bfloat162(h0, h1);
        *(__nv_bfloat162*)(attl + i0) = __halves2bfloat162(l0, l1);
        bf16split(v2, h0, l0); bf16split(v3, h1, l1);
        *(__nv_bfloat162*)(atth + i1) = __halves2bfloat162(h0, h1);
        *(__nv_bfloat162*)(attl + i1) = __halves2bfloat162(l0, l1);
    }
}

// ---------------------------------------------------------------------------
// SIMT SGEMM (only for tiny pre-linear), B stored [N,K] row-major
// ---------------------------------------------------------------------------
__global__ __launch_bounds__(256)
void sgemm_kernel(const float* __restrict__ A, const float* __restrict__ Bm,
                  const float* __restrict__ bias, float* __restrict__ C,
                  int M, int N, int K, int lda, int ldb, int ldc)
{
    __shared__ float As[8][128];
    __shared__ float Bs[8][128];

    const int tid = threadIdx.x;
    const int m0 = blockIdx.y * 128;
    const int n0 = blockIdx.x * 128;

    const int aRow = tid >> 1;
    const int aK   = (tid & 1) << 2;
    const int tr = (tid >> 4) << 3;
    const int tc = (tid & 15) << 3;

    const bool aOK = (m0 + aRow) < M;
    const bool bOK = (n0 + aRow) < N;
    const float* aPtr = A + (long long)(m0 + aRow) * lda + aK;
    const float* bPtr = Bm + (long long)(n0 + aRow) * ldb + aK;

    float acc[8][8];
#pragma unroll
    for (int i = 0; i < 8; i++)
#pragma unroll
        for (int j = 0; j < 8; j++) acc[i][j] = 0.f;

    float4 aReg = make_float4(0.f, 0.f, 0.f, 0.f);
    float4 bReg = make_float4(0.f, 0.f, 0.f, 0.f);
    if (aOK) aReg = *(const float4*)aPtr;
    if (bOK) bReg = *(const float4*)bPtr;

    for (int k0 = 0; k0 < K; k0 += 8) {
        As[aK + 0][aRow] = aReg.x; As[aK + 1][aRow] = aReg.y;
        As[aK + 2][aRow] = aReg.z; As[aK + 3][aRow] = aReg.w;
        Bs[aK + 0][aRow] = bReg.x; Bs[aK + 1][aRow] = bReg.y;
        Bs[aK + 2][aRow] = bReg.z; Bs[aK + 3][aRow] = bReg.w;
        __syncthreads();

        if (k0 + 8 < K) {
            aReg = make_float4(0.f, 0.f, 0.f, 0.f);
            bReg = make_float4(0.f, 0.f, 0.f, 0.f);
            if (aOK) aReg = *(const float4*)(aPtr + (k0 + 8));
            if (bOK) bReg = *(const float4*)(bPtr + (k0 + 8));
        }

#pragma unroll
        for (int kk = 0; kk < 8; kk++) {
            float ar[8], br[8];
            *(float4*)&ar[0] = *(const float4*)&As[kk][tr];
            *(float4*)&ar[4] = *(const float4*)&As[kk][tr + 4];
            *(float4*)&br[0] = *(const float4*)&Bs[kk][tc];
            *(float4*)&br[4] = *(const float4*)&Bs[kk][tc + 4];
#pragma unroll
            for (int i = 0; i < 8; i++)
#pragma unroll
                for (int j = 0; j < 8; j++)
                    acc[i][j] = fmaf(ar[i], br[j], acc[i][j]);
        }
        __syncthreads();
    }

#pragma unroll
    for (int i = 0; i < 8; i++) {
        int gm = m0 + tr + i;
        if (gm < M) {
#pragma unroll
            for (int j = 0; j < 8; j += 4) {
                int gn = n0 + tc + j;
                if (gn < N) {
                    float4 o;
                    o.x = acc[i][j]; o.y = acc[i][j + 1];
                    o.z = acc[i][j + 2]; o.w = acc[i][j + 3];
                    if (bias) {
                        o.x += __ldg(bias + gn);     o.y += __ldg(bias + gn + 1);
                        o.z += __ldg(bias + gn + 2); o.w += __ldg(bias + gn + 3);
                    }
                    *(float4*)(C + (long long)gm * ldc + gn) = o;
                }
            }
        }
    }
}

// ---------------------------------------------------------------------------
// Weight prep: wq||wk single bf16; wv single bf16; w1 split; merge bq||bk
// ---------------------------------------------------------------------------
__global__ void wprep_kernel(const float* __restrict__ wq, const float* __restrict__ wk,
                             const float* __restrict__ wv, const float* __restrict__ w1,
                             const float* __restrict__ bq, const float* __restrict__ bk,
                             float* __restrict__ bqk,
                             __nv_bfloat16* __restrict__ wqkh,
                             __nv_bfloat16* __restrict__ wvh,
                             __nv_bfloat16* __restrict__ w1h, __nv_bfloat16* __restrict__ w1l)
{
    int i = blockIdx.x * 256 + threadIdx.x;
    if (i < 16384) {
        int n = i >> 8, k = i & 255;
        float v = (n < 32) ? wq[n * 256 + k] : wk[(n - 32) * 256 + k];
        wqkh[i] = __float2bfloat16(v);
    } else if (i < 81920) {
        int j = i - 16384;
        wvh[j] = __float2bfloat16(wv[j]);
    } else if (i < 98304) {
        int j = i - 81920;
        __nv_bfloat16 h, l;
        bf16split(w1[j], h, l);
        w1h[j] = h; w1l[j] = l;
    }
    if (i < 64) bqk[i] = (i < 32) ? bq[i] : bk[i - 32];
}

// ---------------------------------------------------------------------------
// x0 moment stats (8 + 36 vals) per batch; deterministic reductions.
// ---------------------------------------------------------------------------
__global__ __launch_bounds__(256)
void xstats_partial(const float* __restrict__ x0, float* __restrict__ pX)
{
    const int b = blockIdx.x, t = threadIdx.x;
    const int warp = t >> 5, lane = t & 31;
    float a[44];
#pragma unroll
    for (int j = 0; j < 44; j++) a[j] = 0.f;

#pragma unroll
    for (int r = 0; r < 4; r++) {
        int l = t + r * 256;
        float v[CIN];
#pragma unroll
        for (int c = 0; c < CIN; c++)
            v[c] = x0[b * (CIN * LL) + c * LL + l];
#pragma unroll
        for (int c = 0; c < CIN; c++) a[c] += v[c];
        int idx = CIN;
#pragma unroll
        for (int c1 = 0; c1 < CIN; c1++)
#pragma unroll
            for (int c2 = c1; c2 < CIN; c2++)
                a[idx++] = fmaf(v[c1], v[c2], a[idx]);
    }
#pragma unroll
    for (int j = 0; j < 44; j++)
#pragma unroll
        for (int o = 16; o; o >>= 1)
            a[j] += __shfl_xor_sync(0xffffffffu, a[j], o);

    __shared__ float ws[8][44];
    if (lane == 0)
#pragma unroll
        for (int j = 0; j < 44; j++) ws[warp][j] = a[j];
    __syncthreads();
    if (t < 44) {
        float s = ws[0][t];
#pragma unroll
        for (int w = 1; w < 8; w++) s += ws[w][t];
        pX[b * 44 + t] = s;
    }
}

__global__ void xstats_final(const float* __restrict__ pX,
                             const float* __restrict__ w0, const float* __restrict__ b0,
                             const float* __restrict__ g0, const float* __restrict__ be0,
                             float* __restrict__ scale, float* __restrict__ shift)
{
    __shared__ float mom[44];
    __shared__ float mu[CIN];
    __shared__ float cov[CIN][CIN];
    const int t = threadIdx.x;
    if (t < 44) {
        float s = 0.f;
        for (int b = 0; b < 64; b++) s += pX[b * 44 + t];
        mom[t] = s;
    }
    __syncthreads();
    if (t == 0) {
        const float inv = 1.f / 65536.f;
        for (int c = 0; c < CIN; c++) mu[c] = mom[c] * inv;
        int idx = CIN;
        for (int c1 = 0; c1 < CIN; c1++)
            for (int c2 = c1; c2 < CIN; c2++) {
                float cv = mom[idx++] * inv - mu[c1] * mu[c2];
                cov[c1][c2] = cv; cov[c2][c1] = cv;
            }
    }
    __syncthreads();
    float w[CIN];
#pragma unroll
    for (int c = 0; c < CIN; c++) w[c] = w0[t * CIN + c];
    float mean = __ldg(b0 + t);
#pragma unroll
    for (int c = 0; c < CIN; c++) mean = fmaf(w[c], mu[c], mean);
    float var = 0.f;
#pragma unroll
    for (int c1 = 0; c1 < CIN; c1++) {
        float acc = 0.f;
#pragma unroll
        for (int c2 = 0; c2 < CIN; c2++) acc = fmaf(w[c2], cov[c1][c2], acc);
        var = fmaf(w[c1], acc, var);
    }
    float sc = __ldg(g0 + t) * rsqrtf(var + 1e-5f);
    scale[t] = sc;
    shift[t] = __ldg(be0 + t) - mean * sc;
}

// ---------------------------------------------------------------------------
// Fused conv0 + BN0 + ReLU -> xah/xal bf16
// ---------------------------------------------------------------------------
__global__ __launch_bounds__(256)
void conv0_fused(const float* __restrict__ x0, const float* __restrict__ w0,
                 const float* __restrict__ b0,
                 const float* __restrict__ sc0, const float* __restrict__ sh0,
                 __nv_bfloat16* __restrict__ xah, __nv_bfloat16* __restrict__ xal)
{
    __shared__ float ws[C0C * CIN];
    __shared__ float xs[CIN][16];
    const int t = threadIdx.x;
    for (int i = t; i < C0C * CIN; i += 256) ws[i] = w0[i];
    const int g0 = blockIdx.x * 16;
    const int b = g0 >> 10, l0 = g0 & 1023;
    if (t < 128) {
        int c = t >> 4, i = t & 15;
        xs[c][i] = x0[b * (CIN * LL) + c * LL + l0 + i];
    }
    __syncthreads();

    float wreg[CIN];
#pragma unroll
    for (int c = 0; c < CIN; c++) wreg[c] = ws[t * CIN + c];
    const float bb = __ldg(b0 + t);
    const float sc = __ldg(sc0 + t), sh = __ldg(sh0 + t);
#pragma unroll
    for (int i = 0; i < 16; i++) {
        float acc = bb;
#pragma unroll
        for (int c = 0; c < CIN; c++) acc = fmaf(wreg[c], xs[c][i], acc);
        float v = fmaxf(fmaf(acc, sc, sh), 0.f);
        __nv_bfloat16 h, l;
        bf16split(v, h, l);
        size_t o = (size_t)(g0 + i) * C0C + t;
        xah[o] = h; xal[o] = l;
    }
}

// ---------------------------------------------------------------------------
// BN stats (deterministic two-stage) — BN1 only
// ---------------------------------------------------------------------------
__global__ __launch_bounds__(256)
void bnstats_partial(const float* __restrict__ y, int nch,
                     float* __restrict__ pS, float* __restrict__ pQ)
{
    const int chunk = blockIdx.x;
    const int group = blockIdx.y;
    const int t = threadIdx.x;
    const int warp = t >> 5, lane = t & 31;
    const int ch = group * 32 + lane;
    const long long base = (long long)chunk * 1024;

    float s = 0.f, q = 0.f;
    for (int r = warp; r < 1024; r += 8) {
        float v = y[(base + r) * nch + ch];
        s += v; q = fmaf(v, v, q);
    }
    __shared__ float ss[8][32], sq[8][32];
    ss[warp][lane] = s; sq[warp][lane] = q;
    __syncthreads();
    if (warp == 0) {
        float S = ss[0][lane], Q = sq[0][lane];
#pragma unroll
        for (int w = 1; w < 8; w++) { S += ss[w][lane]; Q += sq[w][lane]; }
        pS[ch * 64 + chunk] = S;
        pQ[ch * 64 + chunk] = Q;
    }
}

__global__ void bnfinalize(const float* __restrict__ pS, const float* __restrict__ pQ,
                           const float* __restrict__ g, const float* __restrict__ be,
                           float* __restrict__ scale, float* __restrict__ shift, int nch)
{
    int ch = blockIdx.x * blockDim.x + threadIdx.x;
    if (ch >= nch) return;
    float s0 = 0.f, s1 = 0.f, s2 = 0.f, s3 = 0.f;
    float q0 = 0.f, q1 = 0.f, q2 = 0.f, q3 = 0.f;
#pragma unroll
    for (int i = 0; i < 64; i += 4) {
        s0 += pS[ch * 64 + i];     q0 += pQ[ch * 64 + i];
        s1 += pS[ch * 64 + i + 1]; q1 += pQ[ch * 64 + i + 1];
        s2 += pS[ch * 64 + i + 2]; q2 += pQ[ch * 64 + i + 2];
        s3 += pS[ch * 64 + i + 3]; q3 += pQ[ch * 64 + i + 3];
    }
    float s = (s0 + s1) + (s2 + s3);
    float q = (q0 + q1) + (q2 + q3);
    const float inv = 1.f / 65536.f;
    float mean = s * inv;
    float var = q * inv - mean * mean;
    float sc = __ldg(g + ch) * rsqrtf(var + 1e-5f);
    scale[ch] = sc;
    shift[ch] = __ldg(be + ch) - mean * sc;
}

// ---------------------------------------------------------------------------
// Final: out[b][cin][l] = b_out[cin] + sum_f w_out[cin][f] * relu(bn1(x1[g][f]))
// ---------------------------------------------------------------------------
__global__ __launch_bounds__(256)
void final_kernel(const float* __restrict__ x1,
                  const float* __restrict__ scale1, const float* __restrict__ shift1,
                  const float* __restrict__ w_out, const float* __restrict__ b_out,
                  float* __restrict__ out)
{
    __shared__ float xs[32][65];
    __shared__ float wsh[8][64];
    const int t = threadIdx.x;
    const int g0 = blockIdx.x * 32;

    for (int i = t; i < 32 * 64; i += 256) {
        int pos = i >> 6, f = i & 63;
        float v = x1[(size_t)(g0 + pos) * FFC + f];
        v = fmaf(v, __ldg(scale1 + f), __ldg(shift1 + f));
        xs[pos][f] = fmaxf(v, 0.f);
    }
    for (int i = t; i < 8 * 64; i += 256) wsh[i >> 6][i & 63] = w_out[i];
    __syncthreads();

    const int pos = t & 31, cin = t >> 5;
    float acc = __ldg(b_out + cin);
#pragma unroll
    for (int f = 0; f < 64; f++) acc = fmaf(wsh[cin][f], xs[pos][f], acc);

    const int b = g0 >> 10, l0 = g0 & 1023;
    out[b * (CIN * LL) + cin * LL + l0 + pos] = acc;
}

// ---------------------------------------------------------------------------
// Host launcher (graph-capturable: kernel launches only)
// ---------------------------------------------------------------------------
extern "C" void kernel_launch(void* const* d_in, const int* in_sizes, int n_in,
                              void* d_out, int out_size)
{
    const float* z     = (const float*)d_in[0];
    const float* w_pre = (const float*)d_in[1];
    const float* b_pre = (const float*)d_in[2];
    const float* w0    = (const float*)d_in[3];
    const float* b0    = (const float*)d_in[4];
    const float* g0    = (const float*)d_in[5];
    const float* be0   = (const float*)d_in[6];
    const float* wq    = (const float*)d_in[7];
    const float* bq    = (const float*)d_in[8];
    const float* wk    = (const float*)d_in[9];
    const float* bk    = (const float*)d_in[10];
    const float* wv    = (const float*)d_in[11];
    const float* bv    = (const float*)d_in[12];
    const float* gamma = (const float*)d_in[13];
    const float* w1    = (const float*)d_in[14];
    const float* b1    = (const float*)d_in[15];
    const float* g1    = (const float*)d_in[16];
    const float* be1   = (const float*)d_in[17];
    const float* w_out = (const float*)d_in[18];
    const float* b_out = (const float*)d_in[19];
    float* out = (float*)d_out;

    float *x0, *x1, *pS, *pQ, *sc0, *sh0, *sc1, *sh1, *bqk;
    __nv_bfloat16 *xah, *xal, *qkh, *vTh, *atth, *attl;
    __nv_bfloat16 *wqkh, *wvh, *w1h, *w1l;
    cudaGetSymbolAddress((void**)&x0,   g_x0);
    cudaGetSymbolAddress((void**)&xah,  g_xah);
    cudaGetSymbolAddress((void**)&xal,  g_xal);
    cudaGetSymbolAddress((void**)&qkh,  g_qkh);
    cudaGetSymbolAddress((void**)&vTh,  g_vTh);
    cudaGetSymbolAddress((void**)&atth, g_atth);
    cudaGetSymbolAddress((void**)&attl, g_attl);
    cudaGetSymbolAddress((void**)&x1,   g_x1);
    cudaGetSymbolAddress((void**)&pS,   g_pS);
    cudaGetSymbolAddress((void**)&pQ,   g_pQ);
    cudaGetSymbolAddress((void**)&sc0,  g_scale0);
    cudaGetSymbolAddress((void**)&sh0,  g_shift0);
    cudaGetSymbolAddress((void**)&sc1,  g_scale1);
    cudaGetSymbolAddress((void**)&sh1,  g_shift1);
    cudaGetSymbolAddress((void**)&wqkh, g_wqkh);
    cudaGetSymbolAddress((void**)&wvh,  g_wvh);
    cudaGetSymbolAddress((void**)&w1h,  g_w1h);
    cudaGetSymbolAddress((void**)&w1l,  g_w1l);
    cudaGetSymbolAddress((void**)&bqk,  g_bqk);

    const int ST_QK   = 2 * (128 * 80 + 64 * 80);           // 30720 (SPLIT=0)
    const int ST_VP   = 67584;                              // max(2*20480, Ss 128*132*4)
    const int ST_C1   = 2 * (2 * 128 * 80 + 2 * 64 * 80);   // 61440 (SPLIT=1)
    cudaFuncSetAttribute(fa_kernel, cudaFuncAttributeMaxDynamicSharedMemorySize, FA_SMEM);
    cudaFuncSetAttribute(mma_gemm<64, 3, 0>,  cudaFuncAttributeMaxDynamicSharedMemorySize, ST_QK);
    cudaFuncSetAttribute(mma_gemm<128, 2, 0>, cudaFuncAttributeMaxDynamicSharedMemorySize, ST_VP);
    cudaFuncSetAttribute(mma_gemm<64, 0, 1>,  cudaFuncAttributeMaxDynamicSharedMemorySize, ST_C1);

    // 1) pre-linear: x0 = z @ w_pre^T + b_pre   [64 x 8192], K=128
    sgemm_kernel<<<dim3(8192 / 128, 1, 1), 256>>>(
        z, w_pre, b_pre, x0, NB, CIN * LL, ZD, ZD, ZD, CIN * LL);

    // 2) weight prep (independent)
    wprep_kernel<<<384, 256>>>(wq, wk, wv, w1, bq, bk, bqk,
                               wqkh, wvh, w1h, w1l);

    // 3) BN0 via x0 moments (2 MB) -> analytic scale/shift
    xstats_partial<<<64, 256>>>(x0, pS);
    xstats_final<<<1, 256>>>(pS, w0, b0, g0, be0, sc0, sh0);

    // 4) fused conv0 + BN0 + ReLU -> xah/xal bf16
    conv0_fused<<<GG / 16, 256>>>(x0, w0, b0, sc0, sh0, xah, xal);

    // 5) Q+K projection (single bf16 in/out): [g][64], K=256
    mma_gemm<64, 3, 0><<<dim3(1, GG / 128, 1), 256, ST_QK>>>(
        xah, nullptr, C0C, 0, wqkh, nullptr, C0C, 0, bqk,
        nullptr, qkh, nullptr, 64, 0, C0C);

    // 6) V projection (single bf16 in) with fused transpose -> vTh, K=256
    mma_gemm<128, 2, 0><<<dim3(2, GG / 128, 1), 256, ST_VP>>>(
        xah, nullptr, C0C, 0, wvh, nullptr, C0C, 0, bv,
        nullptr, vTh, nullptr, 0, 0, C0C);

    // 7) fused flash attention (R13 register-direct P): att -> bf16 hi/lo
    fa_kernel<<<dim3(8, NB), 256, FA_SMEM>>>(qkh, vTh, xah, xal,
                                             gamma, atth, attl);

    // 8) conv1 (split operands): x1 = att @ w1^T + b1  [g][64], K=256
    mma_gemm<64, 0, 1><<<dim3(1, GG / 128, 1), 256, ST_C1>>>(
        atth, attl, C0C, 0, w1h, w1l, C0C, 0, b1,
        x1, nullptr, nullptr, FFC, 0, C0C);

    // 9) BN1 stats
    bnstats_partial<<<dim3(64, FFC / 32), 256>>>(x1, FFC, pS, pQ);
    bnfinalize<<<1, 64>>>(pS, pQ, g1, be1, sc1, sh1, FFC);

    // 10) fused BN1 + relu + w_out conv -> out [b][8][1024]
    final_kernel<<<GG / 32, 256>>>(x1, sc1, sh1, w_out, b_out, out);

    (void)in_sizes; (void)n_in; (void)out_size;
}

// round 17
// speedup vs baseline: 1.1430x; 1.0495x over previous
#include <cuda_runtime.h>
#include <cuda_bf16.h>

// ---------------------------------------------------------------------------
// Problem constants
// ---------------------------------------------------------------------------
#define NB    64          // batch
#define ZD    128         // latent dim
#define CIN   8
#define LL    1024        // W*H
#define C0C   256         // attention channels
#define CQKC  32
#define FFC   64          // filters
#define GG    65536       // NB * LL (total positions)

// ---------------------------------------------------------------------------
// Device scratch (allocation-free rule: __device__ globals)
// ---------------------------------------------------------------------------
__device__ __align__(16) float g_x0 [NB * CIN * LL];              //  2 MB
__device__ __align__(16) __nv_bfloat16 g_xah[(size_t)GG * C0C];   // 32 MB
__device__ __align__(16) __nv_bfloat16 g_xal[(size_t)GG * C0C];   // 32 MB
__device__ __align__(16) __nv_bfloat16 g_qkh[(size_t)GG * 64];    //  8 MB [g][q32|k32]
__device__ __align__(16) __nv_bfloat16 g_vTh[(size_t)NB * C0C * LL]; // 32 MB V^T bf16
__device__ __align__(16) float g_x1 [(size_t)GG * FFC];           // 16 MB
// weights
__device__ __align__(16) __nv_bfloat16 g_wqkh[64 * C0C];
__device__ __align__(16) __nv_bfloat16 g_wvh [C0C * C0C];
__device__ __align__(16) __nv_bfloat16 g_w1h [FFC * C0C], g_w1l [FFC * C0C];
__device__ __align__(16) float g_bqk[64];
__device__ float g_pS[C0C * 64];           // reused: x0 moment partials [64][44]
__device__ float g_pQ[C0C * 64];
__device__ __align__(16) float g_scale0[C0C], g_shift0[C0C];
__device__ __align__(16) float g_scale1[FFC], g_shift1[FFC];

// ---------------------------------------------------------------------------
// PTX helpers (sm_80-level only — harness ptxas targets plain sm_100)
// ---------------------------------------------------------------------------
__device__ __forceinline__ unsigned smem_u32(const void* p) {
    unsigned a;
    asm("{ .reg .u64 t; cvta.to.shared.u64 t, %1; cvt.u32.u64 %0, t; }" : "=r"(a) : "l"(p));
    return a;
}
__device__ __forceinline__ void cpasync16(unsigned d, const void* s) {
    asm volatile("cp.async.cg.shared.global [%0], [%1], 16;" :: "r"(d), "l"(s));
}
#define CP_COMMIT() asm volatile("cp.async.commit_group;" ::: "memory")
#define CP_WAIT0()  asm volatile("cp.async.wait_group 0;" ::: "memory")
#define CP_WAIT1()  asm volatile("cp.async.wait_group 1;" ::: "memory")

__device__ __forceinline__ void ldsm_x4(unsigned& r0, unsigned& r1,
                                        unsigned& r2, unsigned& r3, unsigned addr) {
    asm volatile("ldmatrix.sync.aligned.m8n8.x4.shared.b16 {%0,%1,%2,%3}, [%4];"
                 : "=r"(r0), "=r"(r1), "=r"(r2), "=r"(r3) : "r"(addr));
}
__device__ __forceinline__ void mma_bf16(float* c, const unsigned* a, const unsigned* b) {
    asm volatile("mma.sync.aligned.m16n8k16.row.col.f32.bf16.bf16.f32 "
                 "{%0,%1,%2,%3}, {%4,%5,%6,%7}, {%8,%9}, {%0,%1,%2,%3};"
                 : "+f"(c[0]), "+f"(c[1]), "+f"(c[2]), "+f"(c[3])
                 : "r"(a[0]), "r"(a[1]), "r"(a[2]), "r"(a[3]), "r"(b[0]), "r"(b[1]));
}
__device__ __forceinline__ void bf16split(float v, __nv_bfloat16& h, __nv_bfloat16& l) {
    h = __float2bfloat16(v);
    l = __float2bfloat16(v - __bfloat162float(h));
}
__device__ __forceinline__ unsigned pack2(__nv_bfloat16 a, __nv_bfloat16 b) {
    return ((unsigned)__bfloat16_as_ushort(b) << 16) | __bfloat16_as_ushort(a);
}
__device__ __forceinline__ unsigned pack2f(float a, float b) {
    return pack2(__float2bfloat16(a), __float2bfloat16(b));
}

// ---------------------------------------------------------------------------
// Generic MMA GEMM, SPLIT in {0,1} (1 = hi/lo 3-pass split operands).
//   OUT_MODE 0: fp32 C (+bias)
//   OUT_MODE 2: V-projection: stage to smem, coalesced transposed vTh write
//   OUT_MODE 3: single bf16 C (+bias)
// ---------------------------------------------------------------------------
template<int BN, int SPLIT>
__device__ __forceinline__ void mm_load(unsigned dst, int t,
    const char* Ah, const char* Al, const char* Bh, const char* Bl,
    int ldaB, int ldbB, int m0, int n0, int kByte)
{
    constexpr int AOP = 128 * 80, BOP = BN * 80;
    constexpr int NA = 512 * (1 + SPLIT);
    constexpr int TC = NA + BN * 4 * (1 + SPLIT);
#pragma unroll
    for (int u = 0; u < TC / 256; u++) {
        int i = t + u * 256;
        if (i < NA) {
            int half = SPLIT ? (i >> 9) : 0;
            int row = (i >> 2) & 127, c = i & 3;
            const char* s = half ? Al : Ah;
            cpasync16(dst + half * AOP + row * 80 + c * 16,
                      s + (size_t)(m0 + row) * ldaB + kByte + c * 16);
        } else {
            int j = i - NA;
            int half = SPLIT ? (j / (BN * 4)) : 0;
            int row = (j >> 2) % BN, c = j & 3;
            const char* s = half ? Bl : Bh;
            cpasync16(dst + (1 + SPLIT) * AOP + half * BOP + row * 80 + c * 16,
                      s + (size_t)(n0 + row) * ldbB + kByte + c * 16);
        }
    }
}

template<int BN, int OUT_MODE, int SPLIT>
__global__ __launch_bounds__(256, 1)
void mma_gemm(const __nv_bfloat16* __restrict__ Ah, const __nv_bfloat16* __restrict__ Al,
              int lda, long long sA,
              const __nv_bfloat16* __restrict__ Bh, const __nv_bfloat16* __restrict__ Bl,
              int ldb, long long sB,
              const float* __restrict__ bias,
              float* __restrict__ C,
              __nv_bfloat16* __restrict__ Ch, __nv_bfloat16* __restrict__ Cl,
              int ldc, long long sC, int K)
{
    constexpr int AOP = 128 * 80, BOP = BN * 80;
    constexpr int BBASE = (1 + SPLIT) * AOP;
    constexpr int ST = (1 + SPLIT) * (AOP + BOP);
    constexpr int NW = BN / 4;
    constexpr int NI = NW / 8;
    constexpr int NGI = NW / 16;

    extern __shared__ char smem[];
    const unsigned sb = smem_u32(smem);
    const int t = threadIdx.x;
    const int n0 = blockIdx.x * BN, m0 = blockIdx.y * 128, z = blockIdx.z;

    const char* cAh = (const char*)(Ah + (size_t)z * sA);
    const char* cAl = SPLIT ? (const char*)(Al + (size_t)z * sA) : cAh;
    const char* cBh = (const char*)(Bh + (size_t)z * sB);
    const char* cBl = SPLIT ? (const char*)(Bl + (size_t)z * sB) : cBh;
    const int ldaB = lda * 2, ldbB = ldb * 2;

    const int w = t >> 5, lane = t & 31;
    const int wm = (w & 1) * 64, wn = (w >> 1) * NW;
    const int aRowSel = (lane & 7) + ((lane >> 3) & 1) * 8;
    const int aChunk  = (lane >> 4) * 16;
    const int bRowSel = (lane & 7) + (lane >> 4) * 8;
    const int bChunk  = ((lane >> 3) & 1) * 16;

    float acc[4][NI][4];
#pragma unroll
    for (int mi = 0; mi < 4; mi++)
#pragma unroll
        for (int ni = 0; ni < NI; ni++)
#pragma unroll
            for (int r = 0; r < 4; r++) acc[mi][ni][r] = 0.f;

    const int nst = K / 32;
    mm_load<BN, SPLIT>(sb, t, cAh, cAl, cBh, cBl, ldaB, ldbB, m0, n0, 0);
    CP_COMMIT();

    for (int s = 0; s < nst; s++) {
        if (s + 1 < nst) {
            mm_load<BN, SPLIT>(sb + ((s + 1) & 1) * ST, t, cAh, cAl, cBh, cBl,
                               ldaB, ldbB, m0, n0, (s + 1) * 64);
            CP_COMMIT();
            CP_WAIT1();
        } else {
            CP_WAIT0();
        }
        __syncthreads();

        const unsigned base = sb + (s & 1) * ST;
#pragma unroll
        for (int s2 = 0; s2 < 2; s2++) {
            unsigned ah[4][4], al[4][4];
#pragma unroll
            for (int mi = 0; mi < 4; mi++) {
                unsigned ar = base + (wm + mi * 16 + aRowSel) * 80 + s2 * 32 + aChunk;
                ldsm_x4(ah[mi][0], ah[mi][1], ah[mi][2], ah[mi][3], ar);
                if (SPLIT) ldsm_x4(al[mi][0], al[mi][1], al[mi][2], al[mi][3], ar + AOP);
            }
            unsigned bh[NI][2], bl[NI][2];
#pragma unroll
            for (int ngi = 0; ngi < NGI; ngi++) {
                unsigned br = base + BBASE + (wn + ngi * 16 + bRowSel) * 80 + s2 * 32 + bChunk;
                unsigned r0, r1, r2, r3;
                ldsm_x4(r0, r1, r2, r3, br);
                bh[2 * ngi][0] = r0; bh[2 * ngi][1] = r1;
                bh[2 * ngi + 1][0] = r2; bh[2 * ngi + 1][1] = r3;
                if (SPLIT) {
                    ldsm_x4(r0, r1, r2, r3, br + BOP);
                    bl[2 * ngi][0] = r0; bl[2 * ngi][1] = r1;
                    bl[2 * ngi + 1][0] = r2; bl[2 * ngi + 1][1] = r3;
                }
            }
#pragma unroll
            for (int mi = 0; mi < 4; mi++)
#pragma unroll
                for (int ni = 0; ni < NI; ni++) {
                    mma_bf16(acc[mi][ni], ah[mi], bh[ni]);
                    if (SPLIT) {
                        mma_bf16(acc[mi][ni], ah[mi], bl[ni]);
                        mma_bf16(acc[mi][ni], al[mi], bh[ni]);
                    }
                }
        }
        __syncthreads();
    }

    const int g = lane >> 2, tg = lane & 3;

    if (OUT_MODE == 2) {
        float* Ss = (float*)smem;
#pragma unroll
        for (int mi = 0; mi < 4; mi++)
#pragma unroll
            for (int ni = 0; ni < NI; ni++) {
                int col = wn + ni * 8 + 2 * tg;
                float b0 = __ldg(bias + n0 + col), b1 = __ldg(bias + n0 + col + 1);
#pragma unroll
                for (int half = 0; half < 2; half++) {
                    int row = wm + mi * 16 + half * 8 + g;
                    Ss[row * 132 + col]     = acc[mi][ni][2 * half + 0] + b0;
                    Ss[row * 132 + col + 1] = acc[mi][ni][2 * half + 1] + b1;
                }
            }
        __syncthreads();
        const int b = m0 >> 10, l0 = m0 & 1023;
        const int m = lane * 4;
#pragma unroll
        for (int i = 0; i < 16; i++) {
            int n = w * 16 + i;
            float v0 = Ss[(m + 0) * 132 + n];
            float v1 = Ss[(m + 1) * 132 + n];
            float v2 = Ss[(m + 2) * 132 + n];
            float v3 = Ss[(m + 3) * 132 + n];
            size_t ob = ((size_t)(b * 256 + n0 + n)) * 1024 + l0 + m;
            uint2 uh;
            uh.x = pack2f(v0, v1);
            uh.y = pack2f(v2, v3);
            *(uint2*)(Ch + ob) = uh;
        }
        return;
    }

#pragma unroll
    for (int mi = 0; mi < 4; mi++) {
#pragma unroll
        for (int ni = 0; ni < NI; ni++) {
            int gr = m0 + wm + mi * 16 + g;
            int gc = n0 + wn + ni * 8 + 2 * tg;
            float b0 = 0.f, b1 = 0.f;
            if (bias) { b0 = __ldg(bias + gc); b1 = __ldg(bias + gc + 1); }
#pragma unroll
            for (int half = 0; half < 2; half++) {
                size_t idx = (size_t)z * sC + (size_t)(gr + half * 8) * ldc + gc;
                float v0 = acc[mi][ni][2 * half + 0] + b0;
                float v1 = acc[mi][ni][2 * half + 1] + b1;
                if (OUT_MODE == 3) {
                    *(unsigned*)(Ch + idx) = pack2f(v0, v1);
                } else {
                    float2 o; o.x = v0; o.y = v1;
                    *(float2*)(C + idx) = o;
                }
            }
        }
    }
}

// ---------------------------------------------------------------------------
// Fused flash attention + conv1 (att never materialized):
//   att = gamma*softmax(QK^T)V + xa   (in registers)
//   x1  = att @ w1^T + b1             (fused epilogue GEMM, 3-pass split)
// Grid (8 m-tiles, 64 b); 256 threads, 8 warps of 16 m-rows.
// smem: Q 10240 | 2 chunk buffers x (K 10240 + V 4x20480) = 194560 B.
// w1 (hi/lo, 80B-pitch staged) prefetched into chunk buffer 0 during last
// chunk's compute (free after ch==6).
// ---------------------------------------------------------------------------
#define FA_CBS  92160
#define FA_SMEM 194560

__device__ __forceinline__ void fa_load_q(unsigned sb, int t, const char* gQ)
{
#pragma unroll
    for (int u = 0; u < 2; u++) {
        int i = t + u * 256;
        int row = i >> 2, c = i & 3;
        cpasync16(sb + row * 80 + c * 16, gQ + (size_t)row * 128 + c * 16);
    }
}

__device__ __forceinline__ void fa_load_chunk(unsigned dst, int t,
    const char* gK, const char* gV, int ch)
{
#pragma unroll
    for (int u = 0; u < 2; u++) {     // K: 128 rows x 64B
        int i = t + u * 256;
        int row = i >> 2, c = i & 3;
        cpasync16(dst + row * 80 + c * 16,
                  gK + (size_t)(ch * 128 + row) * 128 + c * 16);
    }
#pragma unroll
    for (int u = 0; u < 16; u++) {    // V: 4 k-groups x 256 n x 64B
        int i = t + u * 256;
        int c = i & 3, n = (i >> 2) & 255, kg = i >> 10;
        cpasync16(dst + 10240 + kg * 20480 + n * 80 + c * 16,
                  gV + (size_t)n * 2048 + ch * 256 + kg * 64 + c * 16);
    }
}

// stage w1 (64 n x 256 k, hi+lo) at 80B pitch: 8 kg x 64 rows x 64B each op
__device__ __forceinline__ void fa_load_w1(unsigned dst, int t,
    const char* gW1h, const char* gW1l)
{
#pragma unroll
    for (int u = 0; u < 16; u++) {
        int i = t + u * 256;
        int half = i >> 11, j = i & 2047;
        int kg = j >> 8, n = (j >> 2) & 63, c = j & 3;
        const char* s = half ? gW1l : gW1h;
        cpasync16(dst + half * 40960 + kg * 5120 + n * 80 + c * 16,
                  s + (size_t)n * 512 + kg * 64 + c * 16);
    }
}

__global__ __launch_bounds__(256, 1)
void fa_kernel(const __nv_bfloat16* __restrict__ qkh,
               const __nv_bfloat16* __restrict__ vTh,
               const __nv_bfloat16* __restrict__ resh, const __nv_bfloat16* __restrict__ resl,
               const float* __restrict__ gammaPtr,
               const __nv_bfloat16* __restrict__ w1h, const __nv_bfloat16* __restrict__ w1l,
               const float* __restrict__ bias1,
               float* __restrict__ x1)
{
    extern __shared__ char smem[];
    const unsigned sb = smem_u32(smem);
    const int t = threadIdx.x;
    const int m0 = blockIdx.x * 128, b = blockIdx.y;

    const char* gQ = (const char*)qkh + (size_t)(b * 1024 + m0) * 128;
    const char* gK = (const char*)qkh + (size_t)(b * 1024) * 128 + 64;
    const char* gV = (const char*)vTh + (size_t)(b * 256) * 2048;

    const int w = t >> 5, lane = t & 31;
    const int wm = w * 16;
    const int g = lane >> 2, tg = lane & 3;
    const int aRowSel = (lane & 7) + ((lane >> 3) & 1) * 8;
    const int aChunk  = (lane >> 4) * 16;
    const int bRowSel = (lane & 7) + (lane >> 4) * 8;
    const int bChunk  = ((lane >> 3) & 1) * 16;

    float oacc[32][4];
#pragma unroll
    for (int ni = 0; ni < 32; ni++)
#pragma unroll
        for (int r = 0; r < 4; r++) oacc[ni][r] = 0.f;
    float m0r = -1e30f, m1r = -1e30f, z0r = 0.f, z1r = 0.f;

    fa_load_q(sb, t, gQ);
    fa_load_chunk(sb + 10240, t, gK, gV, 0);
    CP_COMMIT();

    for (int ch = 0; ch < 8; ch++) {
        if (ch + 1 < 8) {
            fa_load_chunk(sb + 10240 + ((ch + 1) & 1) * FA_CBS, t, gK, gV, ch + 1);
            CP_COMMIT();
            CP_WAIT1();
        } else {
            // prefetch w1 into free chunk buffer 0 (overlaps last chunk compute);
            // wait_group 1 still guarantees chunk 7's data has arrived.
            fa_load_w1(sb + 10240, t, (const char*)w1h, (const char*)w1l);
            CP_COMMIT();
            CP_WAIT1();
        }
        __syncthreads();

        const unsigned kb = sb + 10240 + (ch & 1) * FA_CBS;

        // ---- S = Q K_chunk^T (single pass), 16m x 128j per warp ----
        float sacc[16][4];
#pragma unroll
        for (int ni = 0; ni < 16; ni++)
#pragma unroll
            for (int r = 0; r < 4; r++) sacc[ni][r] = 0.f;

#pragma unroll
        for (int s2 = 0; s2 < 2; s2++) {
            unsigned qh[4];
            ldsm_x4(qh[0], qh[1], qh[2], qh[3],
                    sb + (wm + aRowSel) * 80 + s2 * 32 + aChunk);
#pragma unroll
            for (int ngi = 0; ngi < 8; ngi++) {
                unsigned br = kb + (ngi * 16 + bRowSel) * 80 + s2 * 32 + bChunk;
                unsigned r0, r1, r2, r3;
                ldsm_x4(r0, r1, r2, r3, br);
                unsigned b0[2] = { r0, r1 }, b1[2] = { r2, r3 };
                mma_bf16(sacc[2 * ngi],     qh, b0);
                mma_bf16(sacc[2 * ngi + 1], qh, b1);
            }
        }

        // ---- online softmax (register + shfl over the 4 tg lanes) ----
        float cm0 = -1e30f, cm1 = -1e30f;
#pragma unroll
        for (int ni = 0; ni < 16; ni++) {
            cm0 = fmaxf(cm0, fmaxf(sacc[ni][0], sacc[ni][1]));
            cm1 = fmaxf(cm1, fmaxf(sacc[ni][2], sacc[ni][3]));
        }
        cm0 = fmaxf(cm0, __shfl_xor_sync(0xffffffffu, cm0, 1));
        cm0 = fmaxf(cm0, __shfl_xor_sync(0xffffffffu, cm0, 2));
        cm1 = fmaxf(cm1, __shfl_xor_sync(0xffffffffu, cm1, 1));
        cm1 = fmaxf(cm1, __shfl_xor_sync(0xffffffffu, cm1, 2));

        float nm0 = fmaxf(m0r, cm0), nm1 = fmaxf(m1r, cm1);
        float sc0 = __expf(m0r - nm0), sc1 = __expf(m1r - nm1);
        float cs0 = 0.f, cs1 = 0.f;
#pragma unroll
        for (int ni = 0; ni < 16; ni++) {
            sacc[ni][0] = __expf(sacc[ni][0] - nm0);
            sacc[ni][1] = __expf(sacc[ni][1] - nm0);
            sacc[ni][2] = __expf(sacc[ni][2] - nm1);
            sacc[ni][3] = __expf(sacc[ni][3] - nm1);
            cs0 += sacc[ni][0] + sacc[ni][1];
            cs1 += sacc[ni][2] + sacc[ni][3];
        }
        cs0 += __shfl_xor_sync(0xffffffffu, cs0, 1);
        cs0 += __shfl_xor_sync(0xffffffffu, cs0, 2);
        cs1 += __shfl_xor_sync(0xffffffffu, cs1, 1);
        cs1 += __shfl_xor_sync(0xffffffffu, cs1, 2);

        z0r = z0r * sc0 + cs0;
        z1r = z1r * sc1 + cs1;
        m0r = nm0; m1r = nm1;
#pragma unroll
        for (int ni = 0; ni < 32; ni++) {
            oacc[ni][0] *= sc0; oacc[ni][1] *= sc0;
            oacc[ni][2] *= sc1; oacc[ni][3] *= sc1;
        }

        // ---- O += P_chunk @ V_chunk (full 256 n; P from C-frag, bf16) ----
#pragma unroll
        for (int u = 0; u < 8; u++) {
            unsigned pa[4];
            pa[0] = pack2f(sacc[2 * u][0],     sacc[2 * u][1]);
            pa[1] = pack2f(sacc[2 * u][2],     sacc[2 * u][3]);
            pa[2] = pack2f(sacc[2 * u + 1][0], sacc[2 * u + 1][1]);
            pa[3] = pack2f(sacc[2 * u + 1][2], sacc[2 * u + 1][3]);
            const unsigned vgb = kb + 10240 + (u >> 1) * 20480;
            const int s2v = u & 1;
#pragma unroll
            for (int ngi = 0; ngi < 16; ngi++) {
                unsigned br = vgb + (ngi * 16 + bRowSel) * 80 + s2v * 32 + bChunk;
                unsigned r0, r1, r2, r3;
                ldsm_x4(r0, r1, r2, r3, br);
                unsigned bv0[2] = { r0, r1 }, bv1[2] = { r2, r3 };
                mma_bf16(oacc[2 * ngi],     pa, bv0);
                mma_bf16(oacc[2 * ngi + 1], pa, bv1);
            }
        }
        __syncthreads();
    }

    // ---- transform oacc in place: att = gamma * O / z + (xah + xal) ----
    const float gam = __ldg(gammaPtr);
    const float gz0 = gam / z0r, gz1 = gam / z1r;
    const int gr0 = b * 1024 + m0 + wm + g;
#pragma unroll
    for (int ni = 0; ni < 32; ni++) {
        int gc = ni * 8 + 2 * tg;
        size_t i0 = (size_t)gr0 * 256 + gc;
        size_t i1 = i0 + (size_t)8 * 256;
        __nv_bfloat162 rh0 = *(const __nv_bfloat162*)(resh + i0);
        __nv_bfloat162 rl0 = *(const __nv_bfloat162*)(resl + i0);
        __nv_bfloat162 rh1 = *(const __nv_bfloat162*)(resh + i1);
        __nv_bfloat162 rl1 = *(const __nv_bfloat162*)(resl + i1);
        oacc[ni][0] = fmaf(gz0, oacc[ni][0], __bfloat162float(rh0.x) + __bfloat162float(rl0.x));
        oacc[ni][1] = fmaf(gz0, oacc[ni][1], __bfloat162float(rh0.y) + __bfloat162float(rl0.y));
        oacc[ni][2] = fmaf(gz1, oacc[ni][2], __bfloat162float(rh1.x) + __bfloat162float(rl1.x));
        oacc[ni][3] = fmaf(gz1, oacc[ni][3], __bfloat162float(rh1.y) + __bfloat162float(rl1.y));
    }

    // ---- fused conv1: x1(16m x 64n) = att(16m x 256k) @ w1^T, 3-pass split ----
    CP_WAIT0();         // w1 staged in chunk buffer 0
    __syncthreads();
    const unsigned W1 = sb + 10240;

    float x1acc[8][4];
#pragma unroll
    for (int ni = 0; ni < 8; ni++)
#pragma unroll
        for (int r = 0; r < 4; r++) x1acc[ni][r] = 0.f;

#pragma unroll
    for (int u = 0; u < 16; u++) {      // k16 steps over 256 att channels
        // A-fragments from att C-frags (identity), hi/lo split in registers
        unsigned pah[4], pal[4];
        {
            __nv_bfloat16 h0, l0, h1, l1;
            bf16split(oacc[2 * u][0], h0, l0); bf16split(oacc[2 * u][1], h1, l1);
            pah[0] = pack2(h0, h1); pal[0] = pack2(l0, l1);
            bf16split(oacc[2 * u][2], h0, l0); bf16split(oacc[2 * u][3], h1, l1);
            pah[1] = pack2(h0, h1); pal[1] = pack2(l0, l1);
            bf16split(oacc[2 * u + 1][0], h0, l0); bf16split(oacc[2 * u + 1][1], h1, l1);
            pah[2] = pack2(h0, h1); pal[2] = pack2(l0, l1);
            bf16split(oacc[2 * u + 1][2], h0, l0); bf16split(oacc[2 * u + 1][3], h1, l1);
            pah[3] = pack2(h0, h1); pal[3] = pack2(l0, l1);
        }
        const int kg = u >> 1, s2 = u & 1;
        unsigned bh[8][2], bl[8][2];
#pragma unroll
        for (int ngi = 0; ngi < 4; ngi++) {
            unsigned br = W1 + kg * 5120 + (ngi * 16 + bRowSel) * 80 + s2 * 32 + bChunk;
            unsigned r0, r1, r2, r3;
            ldsm_x4(r0, r1, r2, r3, br);
            bh[2 * ngi][0] = r0; bh[2 * ngi][1] = r1;
            bh[2 * ngi + 1][0] = r2; bh[2 * ngi + 1][1] = r3;
            ldsm_x4(r0, r1, r2, r3, br + 40960);
            bl[2 * ngi][0] = r0; bl[2 * ngi][1] = r1;
            bl[2 * ngi + 1][0] = r2; bl[2 * ngi + 1][1] = r3;
        }
#pragma unroll
        for (int ni = 0; ni < 8; ni++) {
            mma_bf16(x1acc[ni], pah, bh[ni]);
            mma_bf16(x1acc[ni], pah, bl[ni]);
            mma_bf16(x1acc[ni], pal, bh[ni]);
        }
    }

    // ---- write x1 (+bias), fp32 [g][64] ----
#pragma unroll
    for (int ni = 0; ni < 8; ni++) {
        int gc = ni * 8 + 2 * tg;
        float b0 = __ldg(bias1 + gc), b1v = __ldg(bias1 + gc + 1);
#pragma unroll
        for (int half = 0; half < 2; half++) {
            size_t idx = (size_t)(gr0 + half * 8) * 64 + gc;
            float2 o;
            o.x = x1acc[ni][2 * half + 0] + b0;
            o.y = x1acc[ni][2 * half + 1] + b1v;
            *(float2*)(x1 + idx) = o;
        }
    }
}

// ---------------------------------------------------------------------------
// SIMT SGEMM (only for tiny pre-linear), B stored [N,K] row-major
// ---------------------------------------------------------------------------
__global__ __launch_bounds__(256)
void sgemm_kernel(const float* __restrict__ A, const float* __restrict__ Bm,
                  const float* __restrict__ bias, float* __restrict__ C,
                  int M, int N, int K, int lda, int ldb, int ldc)
{
    __shared__ float As[8][128];
    __shared__ float Bs[8][128];

    const int tid = threadIdx.x;
    const int m0 = blockIdx.y * 128;
    const int n0 = blockIdx.x * 128;

    const int aRow = tid >> 1;
    const int aK   = (tid & 1) << 2;
    const int tr = (tid >> 4) << 3;
    const int tc = (tid & 15) << 3;

    const bool aOK = (m0 + aRow) < M;
    const bool bOK = (n0 + aRow) < N;
    const float* aPtr = A + (long long)(m0 + aRow) * lda + aK;
    const float* bPtr = Bm + (long long)(n0 + aRow) * ldb + aK;

    float acc[8][8];
#pragma unroll
    for (int i = 0; i < 8; i++)
#pragma unroll
        for (int j = 0; j < 8; j++) acc[i][j] = 0.f;

    float4 aReg = make_float4(0.f, 0.f, 0.f, 0.f);
    float4 bReg = make_float4(0.f, 0.f, 0.f, 0.f);
    if (aOK) aReg = *(const float4*)aPtr;
    if (bOK) bReg = *(const float4*)bPtr;

    for (int k0 = 0; k0 < K; k0 += 8) {
        As[aK + 0][aRow] = aReg.x; As[aK + 1][aRow] = aReg.y;
        As[aK + 2][aRow] = aReg.z; As[aK + 3][aRow] = aReg.w;
        Bs[aK + 0][aRow] = bReg.x; Bs[aK + 1][aRow] = bReg.y;
        Bs[aK + 2][aRow] = bReg.z; Bs[aK + 3][aRow] = bReg.w;
        __syncthreads();

        if (k0 + 8 < K) {
            aReg = make_float4(0.f, 0.f, 0.f, 0.f);
            bReg = make_float4(0.f, 0.f, 0.f, 0.f);
            if (aOK) aReg = *(const float4*)(aPtr + (k0 + 8));
            if (bOK) bReg = *(const float4*)(bPtr + (k0 + 8));
        }

#pragma unroll
        for (int kk = 0; kk < 8; kk++) {
            float ar[8], br[8];
            *(float4*)&ar[0] = *(const float4*)&As[kk][tr];
            *(float4*)&ar[4] = *(const float4*)&As[kk][tr + 4];
            *(float4*)&br[0] = *(const float4*)&Bs[kk][tc];
            *(float4*)&br[4] = *(const float4*)&Bs[kk][tc + 4];
#pragma unroll
            for (int i = 0; i < 8; i++)
#pragma unroll
                for (int j = 0; j < 8; j++)
                    acc[i][j] = fmaf(ar[i], br[j], acc[i][j]);
        }
        __syncthreads();
    }

#pragma unroll
    for (int i = 0; i < 8; i++) {
        int gm = m0 + tr + i;
        if (gm < M) {
#pragma unroll
            for (int j = 0; j < 8; j += 4) {
                int gn = n0 + tc + j;
                if (gn < N) {
                    float4 o;
                    o.x = acc[i][j]; o.y = acc[i][j + 1];
                    o.z = acc[i][j + 2]; o.w = acc[i][j + 3];
                    if (bias) {
                        o.x += __ldg(bias + gn);     o.y += __ldg(bias + gn + 1);
                        o.z += __ldg(bias + gn + 2); o.w += __ldg(bias + gn + 3);
                    }
                    *(float4*)(C + (long long)gm * ldc + gn) = o;
                }
            }
        }
    }
}

// ---------------------------------------------------------------------------
// Weight prep: wq||wk single bf16; wv single bf16; w1 split; merge bq||bk
// ---------------------------------------------------------------------------
__global__ void wprep_kernel(const float* __restrict__ wq, const float* __restrict__ wk,
                             const float* __restrict__ wv, const float* __restrict__ w1,
                             const float* __restrict__ bq, const float* __restrict__ bk,
                             float* __restrict__ bqk,
                             __nv_bfloat16* __restrict__ wqkh,
                             __nv_bfloat16* __restrict__ wvh,
                             __nv_bfloat16* __restrict__ w1h, __nv_bfloat16* __restrict__ w1l)
{
    int i = blockIdx.x * 256 + threadIdx.x;
    if (i < 16384) {
        int n = i >> 8, k = i & 255;
        float v = (n < 32) ? wq[n * 256 + k] : wk[(n - 32) * 256 + k];
        wqkh[i] = __float2bfloat16(v);
    } else if (i < 81920) {
        int j = i - 16384;
        wvh[j] = __float2bfloat16(wv[j]);
    } else if (i < 98304) {
        int j = i - 81920;
        __nv_bfloat16 h, l;
        bf16split(w1[j], h, l);
        w1h[j] = h; w1l[j] = l;
    }
    if (i < 64) bqk[i] = (i < 32) ? bq[i] : bk[i - 32];
}

// ---------------------------------------------------------------------------
// x0 moment stats (8 + 36 vals) per batch; deterministic reductions.
// ---------------------------------------------------------------------------
__global__ __launch_bounds__(256)
void xstats_partial(const float* __restrict__ x0, float* __restrict__ pX)
{
    const int b = blockIdx.x, t = threadIdx.x;
    const int warp = t >> 5, lane = t & 31;
    float a[44];
#pragma unroll
    for (int j = 0; j < 44; j++) a[j] = 0.f;

#pragma unroll
    for (int r = 0; r < 4; r++) {
        int l = t + r * 256;
        float v[CIN];
#pragma unroll
        for (int c = 0; c < CIN; c++)
            v[c] = x0[b * (CIN * LL) + c * LL + l];
#pragma unroll
        for (int c = 0; c < CIN; c++) a[c] += v[c];
        int idx = CIN;
#pragma unroll
        for (int c1 = 0; c1 < CIN; c1++)
#pragma unroll
            for (int c2 = c1; c2 < CIN; c2++)
                a[idx++] = fmaf(v[c1], v[c2], a[idx]);
    }
#pragma unroll
    for (int j = 0; j < 44; j++)
#pragma unroll
        for (int o = 16; o; o >>= 1)
            a[j] += __shfl_xor_sync(0xffffffffu, a[j], o);

    __shared__ float ws[8][44];
    if (lane == 0)
#pragma unroll
        for (int j = 0; j < 44; j++) ws[warp][j] = a[j];
    __syncthreads();
    if (t < 44) {
        float s = ws[0][t];
#pragma unroll
        for (int w = 1; w < 8; w++) s += ws[w][t];
        pX[b * 44 + t] = s;
    }
}

__global__ void xstats_final(const float* __restrict__ pX,
                             const float* __restrict__ w0, const float* __restrict__ b0,
                             const float* __restrict__ g0, const float* __restrict__ be0,
                             float* __restrict__ scale, float* __restrict__ shift)
{
    __shared__ float mom[44];
    __shared__ float mu[CIN];
    __shared__ float cov[CIN][CIN];
    const int t = threadIdx.x;
    if (t < 44) {
        float s = 0.f;
        for (int b = 0; b < 64; b++) s += pX[b * 44 + t];
        mom[t] = s;
    }
    __syncthreads();
    if (t == 0) {
        const float inv = 1.f / 65536.f;
        for (int c = 0; c < CIN; c++) mu[c] = mom[c] * inv;
        int idx = CIN;
        for (int c1 = 0; c1 < CIN; c1++)
            for (int c2 = c1; c2 < CIN; c2++) {
                float cv = mom[idx++] * inv - mu[c1] * mu[c2];
                cov[c1][c2] = cv; cov[c2][c1] = cv;
            }
    }
    __syncthreads();
    float w[CIN];
#pragma unroll
    for (int c = 0; c < CIN; c++) w[c] = w0[t * CIN + c];
    float mean = __ldg(b0 + t);
#pragma unroll
    for (int c = 0; c < CIN; c++) mean = fmaf(w[c], mu[c], mean);
    float var = 0.f;
#pragma unroll
    for (int c1 = 0; c1 < CIN; c1++) {
        float acc = 0.f;
#pragma unroll
        for (int c2 = 0; c2 < CIN; c2++) acc = fmaf(w[c2], cov[c1][c2], acc);
        var = fmaf(w[c1], acc, var);
    }
    float sc = __ldg(g0 + t) * rsqrtf(var + 1e-5f);
    scale[t] = sc;
    shift[t] = __ldg(be0 + t) - mean * sc;
}

// ---------------------------------------------------------------------------
// Fused conv0 + BN0 + ReLU -> xah/xal bf16
// ---------------------------------------------------------------------------
__global__ __launch_bounds__(256)
void conv0_fused(const float* __restrict__ x0, const float* __restrict__ w0,
                 const float* __restrict__ b0,
                 const float* __restrict__ sc0, const float* __restrict__ sh0,
                 __nv_bfloat16* __restrict__ xah, __nv_bfloat16* __restrict__ xal)
{
    __shared__ float ws[C0C * CIN];
    __shared__ float xs[CIN][16];
    const int t = threadIdx.x;
    for (int i = t; i < C0C * CIN; i += 256) ws[i] = w0[i];
    const int g0 = blockIdx.x * 16;
    const int b = g0 >> 10, l0 = g0 & 1023;
    if (t < 128) {
        int c = t >> 4, i = t & 15;
        xs[c][i] = x0[b * (CIN * LL) + c * LL + l0 + i];
    }
    __syncthreads();

    float wreg[CIN];
#pragma unroll
    for (int c = 0; c < CIN; c++) wreg[c] = ws[t * CIN + c];
    const float bb = __ldg(b0 + t);
    const float sc = __ldg(sc0 + t), sh = __ldg(sh0 + t);
#pragma unroll
    for (int i = 0; i < 16; i++) {
        float acc = bb;
#pragma unroll
        for (int c = 0; c < CIN; c++) acc = fmaf(wreg[c], xs[c][i], acc);
        float v = fmaxf(fmaf(acc, sc, sh), 0.f);
        __nv_bfloat16 h, l;
        bf16split(v, h, l);
        size_t o = (size_t)(g0 + i) * C0C + t;
        xah[o] = h; xal[o] = l;
    }
}

// ---------------------------------------------------------------------------
// BN stats (deterministic two-stage) — BN1 only
// ---------------------------------------------------------------------------
__global__ __launch_bounds__(256)
void bnstats_partial(const float* __restrict__ y, int nch,
                     float* __restrict__ pS, float* __restrict__ pQ)
{
    const int chunk = blockIdx.x;
    const int group = blockIdx.y;
    const int t = threadIdx.x;
    const int warp = t >> 5, lane = t & 31;
    const int ch = group * 32 + lane;
    const long long base = (long long)chunk * 1024;

    float s = 0.f, q = 0.f;
    for (int r = warp; r < 1024; r += 8) {
        float v = y[(base + r) * nch + ch];
        s += v; q = fmaf(v, v, q);
    }
    __shared__ float ss[8][32], sq[8][32];
    ss[warp][lane] = s; sq[warp][lane] = q;
    __syncthreads();
    if (warp == 0) {
        float S = ss[0][lane], Q = sq[0][lane];
#pragma unroll
        for (int w = 1; w < 8; w++) { S += ss[w][lane]; Q += sq[w][lane]; }
        pS[ch * 64 + chunk] = S;
        pQ[ch * 64 + chunk] = Q;
    }
}

__global__ void bnfinalize(const float* __restrict__ pS, const float* __restrict__ pQ,
                           const float* __restrict__ g, const float* __restrict__ be,
                           float* __restrict__ scale, float* __restrict__ shift, int nch)
{
    int ch = blockIdx.x * blockDim.x + threadIdx.x;
    if (ch >= nch) return;
    float s0 = 0.f, s1 = 0.f, s2 = 0.f, s3 = 0.f;
    float q0 = 0.f, q1 = 0.f, q2 = 0.f, q3 = 0.f;
#pragma unroll
    for (int i = 0; i < 64; i += 4) {
        s0 += pS[ch * 64 + i];     q0 += pQ[ch * 64 + i];
        s1 += pS[ch * 64 + i + 1]; q1 += pQ[ch * 64 + i + 1];
        s2 += pS[ch * 64 + i + 2]; q2 += pQ[ch * 64 + i + 2];
        s3 += pS[ch * 64 + i + 3]; q3 += pQ[ch * 64 + i + 3];
    }
    float s = (s0 + s1) + (s2 + s3);
    float q = (q0 + q1) + (q2 + q3);
    const float inv = 1.f / 65536.f;
    float mean = s * inv;
    float var = q * inv - mean * mean;
    float sc = __ldg(g + ch) * rsqrtf(var + 1e-5f);
    scale[ch] = sc;
    shift[ch] = __ldg(be + ch) - mean * sc;
}

// ---------------------------------------------------------------------------
// Final: out[b][cin][l] = b_out[cin] + sum_f w_out[cin][f] * relu(bn1(x1[g][f]))
// ---------------------------------------------------------------------------
__global__ __launch_bounds__(256)
void final_kernel(const float* __restrict__ x1,
                  const float* __restrict__ scale1, const float* __restrict__ shift1,
                  const float* __restrict__ w_out, const float* __restrict__ b_out,
                  float* __restrict__ out)
{
    __shared__ float xs[32][65];
    __shared__ float wsh[8][64];
    const int t = threadIdx.x;
    const int g0 = blockIdx.x * 32;

    for (int i = t; i < 32 * 64; i += 256) {
        int pos = i >> 6, f = i & 63;
        float v = x1[(size_t)(g0 + pos) * FFC + f];
        v = fmaf(v, __ldg(scale1 + f), __ldg(shift1 + f));
        xs[pos][f] = fmaxf(v, 0.f);
    }
    for (int i = t; i < 8 * 64; i += 256) wsh[i >> 6][i & 63] = w_out[i];
    __syncthreads();

    const int pos = t & 31, cin = t >> 5;
    float acc = __ldg(b_out + cin);
#pragma unroll
    for (int f = 0; f < 64; f++) acc = fmaf(wsh[cin][f], xs[pos][f], acc);

    const int b = g0 >> 10, l0 = g0 & 1023;
    out[b * (CIN * LL) + cin * LL + l0 + pos] = acc;
}

// ---------------------------------------------------------------------------
// Host launcher (graph-capturable: kernel launches only)
// ---------------------------------------------------------------------------
extern "C" void kernel_launch(void* const* d_in, const int* in_sizes, int n_in,
                              void* d_out, int out_size)
{
    const float* z     = (const float*)d_in[0];
    const float* w_pre = (const float*)d_in[1];
    const float* b_pre = (const float*)d_in[2];
    const float* w0    = (const float*)d_in[3];
    const float* b0    = (const float*)d_in[4];
    const float* g0    = (const float*)d_in[5];
    const float* be0   = (const float*)d_in[6];
    const float* wq    = (const float*)d_in[7];
    const float* bq    = (const float*)d_in[8];
    const float* wk    = (const float*)d_in[9];
    const float* bk    = (const float*)d_in[10];
    const float* wv    = (const float*)d_in[11];
    const float* bv    = (const float*)d_in[12];
    const float* gamma = (const float*)d_in[13];
    const float* w1    = (const float*)d_in[14];
    const float* b1    = (const float*)d_in[15];
    const float* g1    = (const float*)d_in[16];
    const float* be1   = (const float*)d_in[17];
    const float* w_out = (const float*)d_in[18];
    const float* b_out = (const float*)d_in[19];
    float* out = (float*)d_out;

    float *x0, *x1, *pS, *pQ, *sc0, *sh0, *sc1, *sh1, *bqk;
    __nv_bfloat16 *xah, *xal, *qkh, *vTh;
    __nv_bfloat16 *wqkh, *wvh, *w1h, *w1l;
    cudaGetSymbolAddress((void**)&x0,   g_x0);
    cudaGetSymbolAddress((void**)&xah,  g_xah);
    cudaGetSymbolAddress((void**)&xal,  g_xal);
    cudaGetSymbolAddress((void**)&qkh,  g_qkh);
    cudaGetSymbolAddress((void**)&vTh,  g_vTh);
    cudaGetSymbolAddress((void**)&x1,   g_x1);
    cudaGetSymbolAddress((void**)&pS,   g_pS);
    cudaGetSymbolAddress((void**)&pQ,   g_pQ);
    cudaGetSymbolAddress((void**)&sc0,  g_scale0);
    cudaGetSymbolAddress((void**)&sh0,  g_shift0);
    cudaGetSymbolAddress((void**)&sc1,  g_scale1);
    cudaGetSymbolAddress((void**)&sh1,  g_shift1);
    cudaGetSymbolAddress((void**)&wqkh, g_wqkh);
    cudaGetSymbolAddress((void**)&wvh,  g_wvh);
    cudaGetSymbolAddress((void**)&w1h,  g_w1h);
    cudaGetSymbolAddress((void**)&w1l,  g_w1l);
    cudaGetSymbolAddress((void**)&bqk,  g_bqk);

    const int ST_QK = 2 * (128 * 80 + 64 * 80);   // 30720 (SPLIT=0)
    const int ST_VP = 67584;                      // max(2*20480, Ss 128*132*4)
    cudaFuncSetAttribute(fa_kernel, cudaFuncAttributeMaxDynamicSharedMemorySize, FA_SMEM);
    cudaFuncSetAttribute(mma_gemm<64, 3, 0>,  cudaFuncAttributeMaxDynamicSharedMemorySize, ST_QK);
    cudaFuncSetAttribute(mma_gemm<128, 2, 0>, cudaFuncAttributeMaxDynamicSharedMemorySize, ST_VP);

    // 1) pre-linear: x0 = z @ w_pre^T + b_pre   [64 x 8192], K=128
    sgemm_kernel<<<dim3(8192 / 128, 1, 1), 256>>>(
        z, w_pre, b_pre, x0, NB, CIN * LL, ZD, ZD, ZD, CIN * LL);

    // 2) weight prep (independent)
    wprep_kernel<<<384, 256>>>(wq, wk, wv, w1, bq, bk, bqk,
                               wqkh, wvh, w1h, w1l);

    // 3) BN0 via x0 moments (2 MB) -> analytic scale/shift
    xstats_partial<<<64, 256>>>(x0, pS);
    xstats_final<<<1, 256>>>(pS, w0, b0, g0, be0, sc0, sh0);

    // 4) fused conv0 + BN0 + ReLU -> xah/xal bf16
    conv0_fused<<<GG / 16, 256>>>(x0, w0, b0, sc0, sh0, xah, xal);

    // 5) Q+K projection (single bf16 in/out): [g][64], K=256
    mma_gemm<64, 3, 0><<<dim3(1, GG / 128, 1), 256, ST_QK>>>(
        xah, nullptr, C0C, 0, wqkh, nullptr, C0C, 0, bqk,
        nullptr, qkh, nullptr, 64, 0, C0C);

    // 6) V projection (single bf16 in) with fused transpose -> vTh, K=256
    mma_gemm<128, 2, 0><<<dim3(2, GG / 128, 1), 256, ST_VP>>>(
        xah, nullptr, C0C, 0, wvh, nullptr, C0C, 0, bv,
        nullptr, vTh, nullptr, 0, 0, C0C);

    // 7) fused flash attention + conv1: x1 directly (att never materialized)
    fa_kernel<<<dim3(8, NB), 256, FA_SMEM>>>(qkh, vTh, xah, xal, gamma,
                                             w1h, w1l, b1, x1);

    // 8) BN1 stats
    bnstats_partial<<<dim3(64, FFC / 32), 256>>>(x1, FFC, pS, pQ);
    bnfinalize<<<1, 64>>>(pS, pQ, g1, be1, sc1, sh1, FFC);

    // 9) fused BN1 + relu + w_out conv -> out [b][8][1024]
    final_kernel<<<GG / 32, 256>>>(x1, sc1, sh1, w_out, b_out, out);

    (void)in_sizes; (void)n_in; (void)out_size;
}